// round 5
// baseline (speedup 1.0000x reference)
#include <cuda_runtime.h>
#include <math.h>

#define BB 512
#define DD 128
#define NLAT 16
#define NLAYER 4
#define NDRUG 25600
#define NENZ 153600
#define RR 64

__device__ float g_lat[BB*NLAT*DD];
__device__ float g_nl [BB*NLAT*DD];
__device__ float g_qp [BB*NLAT*1024];   // [8192][1024] both modalities
__device__ float g_u  [BB*NLAT*1024];
__device__ float g_ffh[BB*NLAT*2*DD];
__device__ float g_h  [BB*DD];
__device__ float g_P  [8*DD*512];       // [l][m][cin 128][512]
__device__ float g_pb [8*512];
__device__ float g_Qt [4*1024*DD];      // [l][c 1024][k 128]
__device__ float g_qb [4*1024];
__device__ float g_M  [4*DD*1024];      // [l][c 128][k 1024]
__device__ float g_mb [4*DD];
__device__ int   g_st [2*(BB+1)];
__device__ int   g_ctr[4];

// ---- packed f32x2 helpers ----
typedef unsigned long long ull;
__device__ __forceinline__ void ffma2(ull &d, ull a, ull b){
    asm("fma.rn.f32x2 %0, %1, %2, %0;" : "+l"(d) : "l"(a), "l"(b));
}
__device__ __forceinline__ void mul2(ull &d, ull s){
    asm("mul.rn.f32x2 %0, %0, %1;" : "+l"(d) : "l"(s));
}
__device__ __forceinline__ ull dup2(float a){
    ull r; asm("mov.b64 %0, {%1,%1};" : "=l"(r) : "f"(a)); return r;
}
__device__ __forceinline__ float2 unp(ull v){
    float2 f; asm("mov.b64 {%0,%1}, %2;" : "=f"(f.x), "=f"(f.y) : "l"(v)); return f;
}

__device__ __forceinline__ int lowb(const int* a, int n, int v){
    int lo=0, hi=n;
    while(lo<hi){int mid=(lo+hi)>>1; if(a[mid]<v) lo=mid+1; else hi=mid;}
    return lo;
}

__global__ void k_starts(const int* db, const int* eb){
    int b=threadIdx.x;
    if(b<BB){ g_st[b]=lowb(db,NDRUG,b); g_st[BB+1+b]=lowb(eb,NENZ,b); }
    if(b==0){ g_st[BB]=NDRUG; g_st[2*BB+1]=NENZ; }
    if(b<4*DD) g_mb[b]=0.f;
    if(b<4) g_ctr[b]=0;
}

__global__ void k_init(const float* lat){
    int i=blockIdx.x*256+threadIdx.x;
    ((float4*)g_lat)[i]=((const float4*)lat)[i&511];
}

// per (l,m,h): P block (Wqm^T Wk /sqrt32), pb, Mtot block (Wo Wv), mb
__global__ void k_pre(const float* mwd,const float* mbd,const float* owd,const float* obd,
                      const float* mwe,const float* mbe,const float* owe,const float* obe){
    int idx=blockIdx.x, l=idx>>3, m=(idx>>2)&1, h=idx&3;
    const float* w =(m?mwe:mwd)+l*3*DD*DD;
    const float* b3=(m?mbe:mbd)+l*3*DD;
    const float* ow=(m?owe:owd)+l*DD*DD;
    const float* ob=(m?obe:obd)+l*DD;
    float* P =g_P +(l*2+m)*DD*512;
    float* pb=g_pb+(l*2+m)*512;
    __shared__ float sA[32*128], sB[32*128];
    int tid=threadIdx.x;
    const float inv=0.17677669529663687f;
    for(int i=tid;i<32*128;i+=256){int j=i>>7,c=i&127;
        sA[i]=w[(h*32+j)*DD+c]; sB[i]=w[(DD+h*32+j)*DD+c];}
    __syncthreads();
    for(int e=tid;e<128*128;e+=256){int c=e>>7,d=e&127; float s=0.f;
        #pragma unroll
        for(int j=0;j<32;j++) s+=sA[j*128+c]*sB[j*128+d];
        P[c*512+h*128+d]=s*inv;}
    if(tid<128){float s=0.f;
        for(int j=0;j<32;j++) s+=b3[h*32+j]*sB[j*128+tid];
        pb[h*128+tid]=s*inv;}
    __syncthreads();
    for(int i=tid;i<32*128;i+=256){int j=i>>7,c=i&127; sB[i]=w[(2*DD+h*32+j)*DD+c];}
    for(int i=tid;i<128*32;i+=256){int c=i>>5,j=i&31; sA[c*32+j]=ow[c*DD+h*32+j];}
    __syncthreads();
    for(int e=tid;e<128*128;e+=256){int c=e>>7,d=e&127; float s=0.f;
        #pragma unroll
        for(int j=0;j<32;j++) s+=sA[c*32+j]*sB[j*128+d];
        g_M[(l*DD+c)*1024 + m*512 + h*128 + d]=s;}
    if(tid<128){float s=(m==0&&h==0)?ob[tid]:0.f;
        for(int j=0;j<32;j++) s+=sA[tid*32+j]*b3[2*DD+h*32+j];
        atomicAdd(&g_mb[l*DD+tid],s);}
}

// Qt[l][c][k] = sum_j wq[m][j][k] * P[l][m][j][c512]; qb = bq@P + pb
__global__ void k_pre2(const float* wqd,const float* bqd,const float* wqe,const float* bqe){
    int idx=blockIdx.x, l=idx>>4, m=(idx>>3)&1, cb=idx&7;  // cb: 64-col chunk within 512
    const float* wq=(m?wqe:wqd)+l*DD*DD;
    const float* bq=(m?bqe:bqd)+l*DD;
    const float* P =g_P +(l*2+m)*DD*512;
    __shared__ float sP[128*64];
    int tid=threadIdx.x;
    for(int i=tid;i<128*64;i+=256){int j=i>>6,cc=i&63; sP[j*64+cc]=P[j*512+cb*64+cc];}
    __syncthreads();
    for(int e=tid;e<64*128;e+=256){
        int cc=e>>7, k=e&127;
        float s=0.f;
        #pragma unroll 8
        for(int j=0;j<128;j++) s+=wq[j*DD+k]*sP[j*64+cc];
        g_Qt[(l*1024 + m*512 + cb*64 + cc)*DD + k]=s;
    }
    if(tid<64){
        float s=g_pb[(l*2+m)*512 + cb*64 + tid];
        for(int j=0;j<128;j++) s+=bq[j]*sP[j*64+tid];
        g_qb[l*1024 + m*512 + cb*64 + tid]=s;
    }
}

// layernorm: 1 warp per 128-d row
__global__ void __launch_bounds__(256) k_ln(const float* x,float* y,const float* g,const float* bb){
    int row=blockIdx.x*8+(threadIdx.x>>5), lane=threadIdx.x&31;
    float4 v=*(const float4*)(x+(size_t)row*DD+lane*4);
    float s=v.x+v.y+v.z+v.w, s2=v.x*v.x+v.y*v.y+v.z*v.z+v.w*v.w;
    #pragma unroll
    for(int o=16;o;o>>=1){s+=__shfl_xor_sync(~0u,s,o); s2+=__shfl_xor_sync(~0u,s2,o);}
    float m=s*(1.f/128.f), var=s2*(1.f/128.f)-m*m, iv=rsqrtf(var+1e-5f);
    float4 gg=*(const float4*)(g+lane*4), b4=*(const float4*)(bb+lane*4);
    float4 o;
    o.x=(v.x-m)*iv*gg.x+b4.x; o.y=(v.y-m)*iv*gg.y+b4.y;
    o.z=(v.z-m)*iv*gg.z+b4.z; o.w=(v.w-m)*iv*gg.w+b4.w;
    *(float4*)(y+(size_t)row*DD+lane*4)=o;
}

// GEMM, FFMA2 lanes paired over k. W row-major [c][k]. M,N mult of 64, K mult of 32.
template<bool ACC,bool RELU>
__global__ void __launch_bounds__(256) k_gemm(const float* A,int lda,const float* W,int ldw,
                                              float* C,int ldc,const float* bias,int K){
    __shared__ float sA[64*36], sB[64*36];
    int rb=blockIdx.x*64, cb=blockIdx.y*64, tid=threadIdx.x;
    int tx=tid&15, ty=tid>>4;
    ull acc2[4][4]={};
    for(int k0=0;k0<K;k0+=32){
        #pragma unroll
        for(int it=0;it<2;it++){
            int i=tid+it*256, row=i>>3, k4=(i&7)<<2;
            *(float4*)&sA[row*36+k4]=*(const float4*)(A+(size_t)(rb+row)*lda+k0+k4);
            *(float4*)&sB[row*36+k4]=*(const float4*)(W+(size_t)(cb+row)*ldw+k0+k4);
        }
        __syncthreads();
        #pragma unroll
        for(int kq=0;kq<32;kq+=4){
            ulonglong2 a0=*(ulonglong2*)&sA[(ty*4+0)*36+kq];
            ulonglong2 a1=*(ulonglong2*)&sA[(ty*4+1)*36+kq];
            ulonglong2 a2=*(ulonglong2*)&sA[(ty*4+2)*36+kq];
            ulonglong2 a3=*(ulonglong2*)&sA[(ty*4+3)*36+kq];
            ulonglong2 b0=*(ulonglong2*)&sB[(tx*4+0)*36+kq];
            ulonglong2 b1=*(ulonglong2*)&sB[(tx*4+1)*36+kq];
            ulonglong2 b2=*(ulonglong2*)&sB[(tx*4+2)*36+kq];
            ulonglong2 b3=*(ulonglong2*)&sB[(tx*4+3)*36+kq];
            ffma2(acc2[0][0],a0.x,b0.x); ffma2(acc2[0][0],a0.y,b0.y);
            ffma2(acc2[0][1],a0.x,b1.x); ffma2(acc2[0][1],a0.y,b1.y);
            ffma2(acc2[0][2],a0.x,b2.x); ffma2(acc2[0][2],a0.y,b2.y);
            ffma2(acc2[0][3],a0.x,b3.x); ffma2(acc2[0][3],a0.y,b3.y);
            ffma2(acc2[1][0],a1.x,b0.x); ffma2(acc2[1][0],a1.y,b0.y);
            ffma2(acc2[1][1],a1.x,b1.x); ffma2(acc2[1][1],a1.y,b1.y);
            ffma2(acc2[1][2],a1.x,b2.x); ffma2(acc2[1][2],a1.y,b2.y);
            ffma2(acc2[1][3],a1.x,b3.x); ffma2(acc2[1][3],a1.y,b3.y);
            ffma2(acc2[2][0],a2.x,b0.x); ffma2(acc2[2][0],a2.y,b0.y);
            ffma2(acc2[2][1],a2.x,b1.x); ffma2(acc2[2][1],a2.y,b1.y);
            ffma2(acc2[2][2],a2.x,b2.x); ffma2(acc2[2][2],a2.y,b2.y);
            ffma2(acc2[2][3],a2.x,b3.x); ffma2(acc2[2][3],a2.y,b3.y);
            ffma2(acc2[3][0],a3.x,b0.x); ffma2(acc2[3][0],a3.y,b0.y);
            ffma2(acc2[3][1],a3.x,b1.x); ffma2(acc2[3][1],a3.y,b1.y);
            ffma2(acc2[3][2],a3.x,b2.x); ffma2(acc2[3][2],a3.y,b2.y);
            ffma2(acc2[3][3],a3.x,b3.x); ffma2(acc2[3][3],a3.y,b3.y);
        }
        __syncthreads();
    }
    int cc=cb+tx*4;
    float4 bv=*(const float4*)(bias+cc);
    #pragma unroll
    for(int i=0;i<4;i++){
        int r=rb+ty*4+i;
        float2 f0=unp(acc2[i][0]), f1=unp(acc2[i][1]), f2=unp(acc2[i][2]), f3=unp(acc2[i][3]);
        float4 v=make_float4(f0.x+f0.y+bv.x, f1.x+f1.y+bv.y, f2.x+f2.y+bv.z, f3.x+f3.y+bv.w);
        if(ACC){
            float4 old=*(float4*)&C[(size_t)r*ldc+cc];
            v.x+=old.x; v.y+=old.y; v.z+=old.z; v.w+=old.w;
        }
        if(RELU){ v.x=fmaxf(v.x,0.f); v.y=fmaxf(v.y,0.f); v.z=fmaxf(v.z,0.f); v.w=fmaxf(v.w,0.f); }
        *(float4*)&C[(size_t)r*ldc+cc]=v;
    }
}

// persistent flash attention over 1024 (modality,batch) items, dynamic scheduling
__global__ void __launch_bounds__(256) k_attn(const float* qp,
                                              const float* kd,const float* vd,
                                              const float* ke,const float* ve,
                                              float* u,int* ctr){
    extern __shared__ float sm[];
    float* sQ=sm;              // [64][128]
    float* sKV=sm+RR*DD;       // [32][132]
    float* sS=sKV+32*132;      // [32 tok][68]  (transposed scores)
    __shared__ float sM[RR], sSum[RR], sScale[RR];
    __shared__ int sItem;
    int tid=threadIdx.x;
    int ty=tid>>4, tx=tid&15;
    int rg=tid>>4, cg=(tid&15)<<3;
    int w=tid>>5, lane=tid&31;

    for(;;){
        if(tid==0) sItem=atomicAdd(ctr,1);
        __syncthreads();
        int item=sItem;
        if(item>=1024) break;
        int isE=item<512;              // enzyme first (longer)
        int b=item&511;
        int mcol=isE?512:0;
        const float* kb=isE?ke:kd;
        const float* vb=isE?ve:vd;
        const int* st=g_st+(isE?(BB+1):0);
        int maxLen=isE?512:128;
        int s0=st[b], len=st[b+1]-s0;
        if(len>maxLen) len=maxLen;
        const float* qpb=qp+(size_t)b*NLAT*1024+mcol;
        float* ub=u+(size_t)b*NLAT*1024+mcol;

        if(len==0){
            for(int i=tid;i<RR*DD/4;i+=256){
                int r=i>>5, c4=(i&31)<<2;
                *(float4*)&ub[(size_t)(r>>2)*1024+(r&3)*128+c4]=make_float4(0.f,0.f,0.f,0.f);
            }
            __syncthreads();
            continue;
        }
        for(int i=tid;i<RR*DD/4;i+=256){
            int r=i>>5, c4=(i&31)<<2;
            *(float4*)&sQ[r*DD+c4]=*(const float4*)(qpb+(size_t)(r>>2)*1024+(r&3)*128+c4);
        }
        if(tid<RR){ sM[tid]=-1e30f; sSum[tid]=0.f; }
        __syncthreads();

        ull acc[4][4]={};
        for(int t0=0;t0<len;t0+=32){
            int tc=min(32,len-t0);
            for(int i=tid;i<tc*32;i+=256){
                int row=i>>5, c4=(i&31)<<2;
                *(float4*)&sKV[row*132+c4]=*(const float4*)(kb+(size_t)(s0+t0+row)*DD+c4);
            }
            __syncthreads();
            { // scores: lanes paired over d
                ull sc2[4][2]={};
                #pragma unroll 8
                for(int d=0;d<DD;d+=4){
                    ulonglong2 k0=*(ulonglong2*)&sKV[(tx*2)*132+d];
                    ulonglong2 k1=*(ulonglong2*)&sKV[(tx*2+1)*132+d];
                    #pragma unroll
                    for(int i=0;i<4;i++){
                        ulonglong2 q2=*(ulonglong2*)&sQ[(ty*4+i)*DD+d];
                        ffma2(sc2[i][0],q2.x,k0.x); ffma2(sc2[i][0],q2.y,k0.y);
                        ffma2(sc2[i][1],q2.x,k1.x); ffma2(sc2[i][1],q2.y,k1.y);
                    }
                }
                #pragma unroll
                for(int i=0;i<4;i++)
                    #pragma unroll
                    for(int j=0;j<2;j++){
                        int t=tx*2+j;
                        float2 f=unp(sc2[i][j]);
                        sS[t*68+ty*4+i]=(t<tc)?(f.x+f.y):-1e30f;  // transposed [t][r]
                    }
            }
            __syncthreads();
            // online softmax (8 warps x 8 rows)
            for(int r=w;r<RR;r+=8){
                float x=sS[lane*68+r];
                float tm=x;
                #pragma unroll
                for(int o=16;o;o>>=1) tm=fmaxf(tm,__shfl_xor_sync(~0u,tm,o));
                float mOld=sM[r], mNew=fmaxf(mOld,tm);
                float e=__expf(x-mNew);
                float ts=e;
                #pragma unroll
                for(int o=16;o;o>>=1) ts+=__shfl_xor_sync(~0u,ts,o);
                sS[lane*68+r]=e;
                if(lane==0){
                    float sc=__expf(mOld-mNew);
                    sScale[r]=sc;
                    sSum[r]=sSum[r]*sc+ts;
                    sM[r]=mNew;
                }
            }
            // load V into same buffer
            for(int i=tid;i<tc*32;i+=256){
                int row=i>>5, c4=(i&31)<<2;
                *(float4*)&sKV[row*132+c4]=*(const float4*)(vb+(size_t)(s0+t0+row)*DD+c4);
            }
            __syncthreads();
            #pragma unroll
            for(int i=0;i<4;i++){
                ull sc2=dup2(sScale[rg*4+i]);
                #pragma unroll
                for(int p=0;p<4;p++) mul2(acc[i][p],sc2);
            }
            for(int t=0;t<tc;t++){
                ulonglong2 v0=*(ulonglong2*)&sKV[t*132+cg];
                ulonglong2 v1=*(ulonglong2*)&sKV[t*132+cg+4];
                float4 s4=*(float4*)&sS[t*68+rg*4];
                ull a0=dup2(s4.x), a1=dup2(s4.y), a2=dup2(s4.z), a3=dup2(s4.w);
                ffma2(acc[0][0],a0,v0.x); ffma2(acc[0][1],a0,v0.y);
                ffma2(acc[0][2],a0,v1.x); ffma2(acc[0][3],a0,v1.y);
                ffma2(acc[1][0],a1,v0.x); ffma2(acc[1][1],a1,v0.y);
                ffma2(acc[1][2],a1,v1.x); ffma2(acc[1][3],a1,v1.y);
                ffma2(acc[2][0],a2,v0.x); ffma2(acc[2][1],a2,v0.y);
                ffma2(acc[2][2],a2,v1.x); ffma2(acc[2][3],a2,v1.y);
                ffma2(acc[3][0],a3,v0.x); ffma2(acc[3][1],a3,v0.y);
                ffma2(acc[3][2],a3,v1.x); ffma2(acc[3][3],a3,v1.y);
            }
            __syncthreads();
        }
        #pragma unroll
        for(int i=0;i<4;i++){
            int r=rg*4+i;
            float iv=1.f/sSum[r];
            float* dst=&ub[(size_t)(r>>2)*1024+(r&3)*128+cg];
            float2 f0=unp(acc[i][0]), f1=unp(acc[i][1]), f2=unp(acc[i][2]), f3=unp(acc[i][3]);
            *(float4*)dst    =make_float4(f0.x*iv,f0.y*iv,f1.x*iv,f1.y*iv);
            *(float4*)(dst+4)=make_float4(f2.x*iv,f2.y*iv,f3.x*iv,f3.y*iv);
        }
        __syncthreads();
    }
}

__global__ void __launch_bounds__(128) k_head2(const float* h,const float* w2,const float* b2,float* out){
    int b=blockIdx.x, c=threadIdx.x;
    float s=h[(size_t)b*DD+c]*w2[c];
    #pragma unroll
    for(int o=16;o;o>>=1) s+=__shfl_xor_sync(~0u,s,o);
    __shared__ float red[4];
    if((c&31)==0) red[c>>5]=s;
    __syncthreads();
    if(c==0){
        float t=red[0]+red[1]+red[2]+red[3]+b2[0];
        out[b]=fmaxf(t,0.f)+log1pf(__expf(-fabsf(t)));
    }
}

extern "C" void kernel_launch(void* const* d_in, const int* in_sizes, int n_in,
                              void* d_out, int out_size){
    (void)in_sizes;(void)n_in;(void)out_size;
    const float* drug_k=(const float*)d_in[0];
    const float* drug_v=(const float*)d_in[1];
    const float* enz_k =(const float*)d_in[2];
    const float* enz_v =(const float*)d_in[3];
    const int*   db    =(const int*)d_in[4];
    const int*   eb    =(const int*)d_in[5];
    const float* lat   =(const float*)d_in[6];
    const float* wq_d=(const float*)d_in[7];  const float* bq_d=(const float*)d_in[8];
    const float* wq_e=(const float*)d_in[9];  const float* bq_e=(const float*)d_in[10];
    const float* mw_d=(const float*)d_in[11]; const float* mb_d=(const float*)d_in[12];
    const float* ow_d=(const float*)d_in[13]; const float* ob_d=(const float*)d_in[14];
    const float* mw_e=(const float*)d_in[15]; const float* mb_e=(const float*)d_in[16];
    const float* ow_e=(const float*)d_in[17]; const float* ob_e=(const float*)d_in[18];
    const float* l1g=(const float*)d_in[19];  const float* l1b=(const float*)d_in[20];
    const float* l2g=(const float*)d_in[21];  const float* l2b=(const float*)d_in[22];
    const float* fw1=(const float*)d_in[23];  const float* fb1=(const float*)d_in[24];
    const float* fw2=(const float*)d_in[25];  const float* fb2=(const float*)d_in[26];
    const float* hw1=(const float*)d_in[27];  const float* hb1=(const float*)d_in[28];
    const float* hw2=(const float*)d_in[29];  const float* hb2=(const float*)d_in[30];
    float* out=(float*)d_out;

    static float *p_lat,*p_nl,*p_qp,*p_u,*p_ffh,*p_h,*p_Qt,*p_qb,*p_M,*p_mb; static int* p_ctr;
    static bool init=false;
    if(!init){
        cudaGetSymbolAddress((void**)&p_lat,g_lat); cudaGetSymbolAddress((void**)&p_nl,g_nl);
        cudaGetSymbolAddress((void**)&p_qp,g_qp);   cudaGetSymbolAddress((void**)&p_u,g_u);
        cudaGetSymbolAddress((void**)&p_ffh,g_ffh); cudaGetSymbolAddress((void**)&p_h,g_h);
        cudaGetSymbolAddress((void**)&p_Qt,g_Qt);   cudaGetSymbolAddress((void**)&p_qb,g_qb);
        cudaGetSymbolAddress((void**)&p_M,g_M);     cudaGetSymbolAddress((void**)&p_mb,g_mb);
        cudaGetSymbolAddress((void**)&p_ctr,g_ctr);
        cudaFuncSetAttribute(k_attn,cudaFuncAttributeMaxDynamicSharedMemorySize,60000);
        init=true;
    }
    k_starts<<<1,1024>>>(db,eb);
    k_pre<<<32,256>>>(mw_d,mb_d,ow_d,ob_d,mw_e,mb_e,ow_e,ob_e);
    k_pre2<<<64,256>>>(wq_d,bq_d,wq_e,bq_e);
    k_init<<<1024,256>>>(lat);

    const int smemA=(RR*DD+32*132+32*68)*4;  // 58368
    for(int l=0;l<NLAYER;l++){
        k_ln<<<1024,256>>>(p_lat,p_nl,l1g+l*DD,l1b+l*DD);
        // qp[8192][1024] = nl @ Qt^T + qb  (both modalities)
        k_gemm<false,false><<<dim3(128,16),256>>>(p_nl,DD,p_Qt+l*1024*DD,DD,p_qp,1024,p_qb+l*1024,DD);
        k_attn<<<444,256,smemA>>>(p_qp,drug_k,drug_v,enz_k,enz_v,p_u,p_ctr+l);
        // lat += u @ M^T + mb  (K=1024 covers both modalities)
        k_gemm<true,false><<<dim3(128,2),256>>>(p_u,1024,p_M+l*DD*1024,1024,p_lat,DD,p_mb+l*DD,1024);
        k_ln<<<1024,256>>>(p_lat,p_nl,l2g+l*DD,l2b+l*DD);
        k_gemm<false,true><<<dim3(128,4),256>>>(p_nl,DD,fw1+l*2*DD*DD,DD,p_ffh,2*DD,fb1+l*2*DD,DD);
        k_gemm<true,false><<<dim3(128,2),256>>>(p_ffh,2*DD,fw2+l*2*DD*DD,2*DD,p_lat,DD,fb2+l*DD,2*DD);
    }
    k_gemm<false,true><<<dim3(8,2),256>>>(p_lat,NLAT*DD,hw1,NLAT*DD,p_h,DD,hb1,NLAT*DD);
    k_head2<<<BB,128>>>(p_h,hw2,hb2,out);
}

// round 6
// speedup vs baseline: 1.3971x; 1.3971x over previous
#include <cuda_runtime.h>
#include <math.h>

#define BB 512
#define DD 128
#define NLAT 16
#define NLAYER 4
#define NDRUG 25600
#define NENZ 153600
#define RR 64

__device__ float g_lat[BB*NLAT*DD];
__device__ float g_nl [BB*NLAT*DD];
__device__ float g_qp [BB*NLAT*1024];   // [8192][1024] both modalities
__device__ float g_u  [BB*NLAT*1024];
__device__ float g_ffh[BB*NLAT*2*DD];
__device__ float g_h  [BB*DD];
__device__ float g_P  [8*DD*512];       // [l][m][cin 128][512]
__device__ float g_pb [8*512];
__device__ float g_Qt [4*1024*DD];      // [l][c 1024][k 128]
__device__ float g_qb [4*1024];
__device__ float g_M  [4*DD*1024];      // [l][c 128][k 1024]
__device__ float g_mb [4*DD];
__device__ int   g_st [2*(BB+1)];
__device__ int   g_ctr[4];

// ---- packed f32x2 helpers ----
typedef unsigned long long ull;
__device__ __forceinline__ void ffma2(ull &d, ull a, ull b){
    asm("fma.rn.f32x2 %0, %1, %2, %0;" : "+l"(d) : "l"(a), "l"(b));
}
__device__ __forceinline__ void mul2(ull &d, ull s){
    asm("mul.rn.f32x2 %0, %0, %1;" : "+l"(d) : "l"(s));
}
__device__ __forceinline__ ull dup2(float a){
    ull r; asm("mov.b64 %0, {%1,%1};" : "=l"(r) : "f"(a)); return r;
}
__device__ __forceinline__ float2 unp(ull v){
    float2 f; asm("mov.b64 {%0,%1}, %2;" : "=f"(f.x), "=f"(f.y) : "l"(v)); return f;
}

__device__ __forceinline__ int lowb(const int* a, int n, int v){
    int lo=0, hi=n;
    while(lo<hi){int mid=(lo+hi)>>1; if(a[mid]<v) lo=mid+1; else hi=mid;}
    return lo;
}

__global__ void k_starts(const int* db, const int* eb){
    int b=threadIdx.x;
    if(b<BB){ g_st[b]=lowb(db,NDRUG,b); g_st[BB+1+b]=lowb(eb,NENZ,b); }
    if(b==0){ g_st[BB]=NDRUG; g_st[2*BB+1]=NENZ; }
    if(b<4*DD) g_mb[b]=0.f;
    if(b<4) g_ctr[b]=0;
}

__global__ void k_init(const float* lat){
    int i=blockIdx.x*256+threadIdx.x;
    ((float4*)g_lat)[i]=((const float4*)lat)[i&511];
}

// per (l,m,h): P block (Wqm^T Wk /sqrt32), pb, M block (Wo Wv), mb
__global__ void k_pre(const float* mwd,const float* mbd,const float* owd,const float* obd,
                      const float* mwe,const float* mbe,const float* owe,const float* obe){
    int idx=blockIdx.x, l=idx>>3, m=(idx>>2)&1, h=idx&3;
    const float* w =(m?mwe:mwd)+l*3*DD*DD;
    const float* b3=(m?mbe:mbd)+l*3*DD;
    const float* ow=(m?owe:owd)+l*DD*DD;
    const float* ob=(m?obe:obd)+l*DD;
    float* P =g_P +(l*2+m)*DD*512;
    float* pb=g_pb+(l*2+m)*512;
    __shared__ float sA[32*128], sB[32*128];
    int tid=threadIdx.x;
    const float inv=0.17677669529663687f;
    for(int i=tid;i<32*128;i+=256){int j=i>>7,c=i&127;
        sA[i]=w[(h*32+j)*DD+c]; sB[i]=w[(DD+h*32+j)*DD+c];}
    __syncthreads();
    for(int e=tid;e<128*128;e+=256){int c=e>>7,d=e&127; float s=0.f;
        #pragma unroll
        for(int j=0;j<32;j++) s+=sA[j*128+c]*sB[j*128+d];
        P[c*512+h*128+d]=s*inv;}
    if(tid<128){float s=0.f;
        for(int j=0;j<32;j++) s+=b3[h*32+j]*sB[j*128+tid];
        pb[h*128+tid]=s*inv;}
    __syncthreads();
    for(int i=tid;i<32*128;i+=256){int j=i>>7,c=i&127; sB[i]=w[(2*DD+h*32+j)*DD+c];}
    for(int i=tid;i<128*32;i+=256){int c=i>>5,j=i&31; sA[c*32+j]=ow[c*DD+h*32+j];}
    __syncthreads();
    for(int e=tid;e<128*128;e+=256){int c=e>>7,d=e&127; float s=0.f;
        #pragma unroll
        for(int j=0;j<32;j++) s+=sA[c*32+j]*sB[j*128+d];
        g_M[(l*DD+c)*1024 + m*512 + h*128 + d]=s;}
    if(tid<128){float s=(m==0&&h==0)?ob[tid]:0.f;
        for(int j=0;j<32;j++) s+=sA[tid*32+j]*b3[2*DD+h*32+j];
        atomicAdd(&g_mb[l*DD+tid],s);}
}

// Qt[l][c][k] = sum_j wq[m][j][k] * P[l][m][j][c512]; qb = bq@P + pb
__global__ void k_pre2(const float* wqd,const float* bqd,const float* wqe,const float* bqe){
    int idx=blockIdx.x, l=idx>>4, m=(idx>>3)&1, cb=idx&7;
    const float* wq=(m?wqe:wqd)+l*DD*DD;
    const float* bq=(m?bqe:bqd)+l*DD;
    const float* P =g_P +(l*2+m)*DD*512;
    __shared__ float sP[128*64];
    int tid=threadIdx.x;
    for(int i=tid;i<128*64;i+=256){int j=i>>6,cc=i&63; sP[j*64+cc]=P[j*512+cb*64+cc];}
    __syncthreads();
    for(int e=tid;e<64*128;e+=256){
        int cc=e>>7, k=e&127;
        float s=0.f;
        #pragma unroll 8
        for(int j=0;j<128;j++) s+=wq[j*DD+k]*sP[j*64+cc];
        g_Qt[(l*1024 + m*512 + cb*64 + cc)*DD + k]=s;
    }
    if(tid<64){
        float s=g_pb[(l*2+m)*512 + cb*64 + tid];
        for(int j=0;j<128;j++) s+=bq[j]*sP[j*64+tid];
        g_qb[l*1024 + m*512 + cb*64 + tid]=s;
    }
}

// layernorm: 1 warp per 128-d row
__global__ void __launch_bounds__(256) k_ln(const float* x,float* y,const float* g,const float* bb){
    int row=blockIdx.x*8+(threadIdx.x>>5), lane=threadIdx.x&31;
    float4 v=*(const float4*)(x+(size_t)row*DD+lane*4);
    float s=v.x+v.y+v.z+v.w, s2=v.x*v.x+v.y*v.y+v.z*v.z+v.w*v.w;
    #pragma unroll
    for(int o=16;o;o>>=1){s+=__shfl_xor_sync(~0u,s,o); s2+=__shfl_xor_sync(~0u,s2,o);}
    float m=s*(1.f/128.f), var=s2*(1.f/128.f)-m*m, iv=rsqrtf(var+1e-5f);
    float4 gg=*(const float4*)(g+lane*4), b4=*(const float4*)(bb+lane*4);
    float4 o;
    o.x=(v.x-m)*iv*gg.x+b4.x; o.y=(v.y-m)*iv*gg.y+b4.y;
    o.z=(v.z-m)*iv*gg.z+b4.z; o.w=(v.w-m)*iv*gg.w+b4.w;
    *(float4*)(y+(size_t)row*DD+lane*4)=o;
}

// GEMM, FFMA2 lanes paired over k, conflict-free interleaved fragment mapping.
// W row-major [c][k]. M,N multiples of 64, K multiple of 32.
// Thread (tx,ty) owns rows rb+ty+{0,16,32,48}, cols cb+tx+{0,16,32,48}.
template<bool ACC,bool RELU>
__global__ void __launch_bounds__(256) k_gemm(const float* A,int lda,const float* W,int ldw,
                                              float* C,int ldc,const float* bias,int K){
    __shared__ float sA[64*36], sB[64*36];
    int rb=blockIdx.x*64, cb=blockIdx.y*64, tid=threadIdx.x;
    int tx=tid&15, ty=tid>>4;
    ull acc2[4][4]={};
    for(int k0=0;k0<K;k0+=32){
        #pragma unroll
        for(int it=0;it<2;it++){
            int i=tid+it*256, row=i>>3, k4=(i&7)<<2;
            *(float4*)&sA[row*36+k4]=*(const float4*)(A+(size_t)(rb+row)*lda+k0+k4);
            *(float4*)&sB[row*36+k4]=*(const float4*)(W+(size_t)(cb+row)*ldw+k0+k4);
        }
        __syncthreads();
        #pragma unroll
        for(int kq=0;kq<32;kq+=4){
            ulonglong2 a[4], b[4];
            #pragma unroll
            for(int j=0;j<4;j++){
                a[j]=*(ulonglong2*)&sA[(ty+16*j)*36+kq];  // broadcast per half-warp
                b[j]=*(ulonglong2*)&sB[(tx+16*j)*36+kq];  // conflict-free: tx*36 mod 32 = tx*4
            }
            #pragma unroll
            for(int i=0;i<4;i++)
                #pragma unroll
                for(int j=0;j<4;j++){
                    ffma2(acc2[i][j],a[i].x,b[j].x);
                    ffma2(acc2[i][j],a[i].y,b[j].y);
                }
        }
        __syncthreads();
    }
    #pragma unroll
    for(int i=0;i<4;i++){
        int r=rb+ty+16*i;
        #pragma unroll
        for(int j=0;j<4;j++){
            int c=cb+tx+16*j;
            float2 f=unp(acc2[i][j]);
            float v=f.x+f.y+bias[c];
            if(ACC) v+=C[(size_t)r*ldc+c];
            if(RELU) v=fmaxf(v,0.f);
            C[(size_t)r*ldc+c]=v;
        }
    }
}

// persistent flash attention over 1024 (modality,batch) items, dynamic scheduling
__global__ void __launch_bounds__(256) k_attn(const float* qp,
                                              const float* kd,const float* vd,
                                              const float* ke,const float* ve,
                                              float* u,int* ctr){
    extern __shared__ float sm[];
    float* sQ=sm;              // [64][128]
    float* sKV=sm+RR*DD;       // [32][132]
    float* sS=sKV+32*132;      // [32 tok][68]  (transposed scores)
    __shared__ float sM[RR], sSum[RR], sScale[RR];
    __shared__ int sItem;
    int tid=threadIdx.x;
    int ty=tid>>4, tx=tid&15;
    int rg=tid>>4, cg=(tid&15)<<3;
    int w=tid>>5, lane=tid&31;

    for(;;){
        if(tid==0) sItem=atomicAdd(ctr,1);
        __syncthreads();
        int item=sItem;
        if(item>=1024) break;
        int isE=item<512;              // enzyme first (longer)
        int b=item&511;
        int mcol=isE?512:0;
        const float* kb=isE?ke:kd;
        const float* vb=isE?ve:vd;
        const int* st=g_st+(isE?(BB+1):0);
        int maxLen=isE?512:128;
        int s0=st[b], len=st[b+1]-s0;
        if(len>maxLen) len=maxLen;
        const float* qpb=qp+(size_t)b*NLAT*1024+mcol;
        float* ub=u+(size_t)b*NLAT*1024+mcol;

        if(len==0){
            for(int i=tid;i<RR*DD/4;i+=256){
                int r=i>>5, c4=(i&31)<<2;
                *(float4*)&ub[(size_t)(r>>2)*1024+(r&3)*128+c4]=make_float4(0.f,0.f,0.f,0.f);
            }
            __syncthreads();
            continue;
        }
        for(int i=tid;i<RR*DD/4;i+=256){
            int r=i>>5, c4=(i&31)<<2;
            *(float4*)&sQ[r*DD+c4]=*(const float4*)(qpb+(size_t)(r>>2)*1024+(r&3)*128+c4);
        }
        if(tid<RR){ sM[tid]=-1e30f; sSum[tid]=0.f; }
        __syncthreads();

        ull acc[4][4]={};
        for(int t0=0;t0<len;t0+=32){
            int tc=min(32,len-t0);
            for(int i=tid;i<tc*32;i+=256){
                int row=i>>5, c4=(i&31)<<2;
                *(float4*)&sKV[row*132+c4]=*(const float4*)(kb+(size_t)(s0+t0+row)*DD+c4);
            }
            __syncthreads();
            { // scores: lanes paired over d
                ull sc2[4][2]={};
                #pragma unroll 8
                for(int d=0;d<DD;d+=4){
                    ulonglong2 k0=*(ulonglong2*)&sKV[(tx*2)*132+d];
                    ulonglong2 k1=*(ulonglong2*)&sKV[(tx*2+1)*132+d];
                    #pragma unroll
                    for(int i=0;i<4;i++){
                        ulonglong2 q2=*(ulonglong2*)&sQ[(ty*4+i)*DD+d];
                        ffma2(sc2[i][0],q2.x,k0.x); ffma2(sc2[i][0],q2.y,k0.y);
                        ffma2(sc2[i][1],q2.x,k1.x); ffma2(sc2[i][1],q2.y,k1.y);
                    }
                }
                #pragma unroll
                for(int i=0;i<4;i++)
                    #pragma unroll
                    for(int j=0;j<2;j++){
                        int t=tx*2+j;
                        float2 f=unp(sc2[i][j]);
                        sS[t*68+ty*4+i]=(t<tc)?(f.x+f.y):-1e30f;  // transposed [t][r]
                    }
            }
            __syncthreads();
            // online softmax (8 warps x 8 rows)
            for(int r=w;r<RR;r+=8){
                float x=sS[lane*68+r];
                float tm=x;
                #pragma unroll
                for(int o=16;o;o>>=1) tm=fmaxf(tm,__shfl_xor_sync(~0u,tm,o));
                float mOld=sM[r], mNew=fmaxf(mOld,tm);
                float e=__expf(x-mNew);
                float ts=e;
                #pragma unroll
                for(int o=16;o;o>>=1) ts+=__shfl_xor_sync(~0u,ts,o);
                sS[lane*68+r]=e;
                if(lane==0){
                    float sc=__expf(mOld-mNew);
                    sScale[r]=sc;
                    sSum[r]=sSum[r]*sc+ts;
                    sM[r]=mNew;
                }
            }
            // load V into same buffer
            for(int i=tid;i<tc*32;i+=256){
                int row=i>>5, c4=(i&31)<<2;
                *(float4*)&sKV[row*132+c4]=*(const float4*)(vb+(size_t)(s0+t0+row)*DD+c4);
            }
            __syncthreads();
            #pragma unroll
            for(int i=0;i<4;i++){
                ull sc2=dup2(sScale[rg*4+i]);
                #pragma unroll
                for(int p=0;p<4;p++) mul2(acc[i][p],sc2);
            }
            for(int t=0;t<tc;t++){
                ulonglong2 v0=*(ulonglong2*)&sKV[t*132+cg];
                ulonglong2 v1=*(ulonglong2*)&sKV[t*132+cg+4];
                float4 s4=*(float4*)&sS[t*68+rg*4];
                ull a0=dup2(s4.x), a1=dup2(s4.y), a2=dup2(s4.z), a3=dup2(s4.w);
                ffma2(acc[0][0],a0,v0.x); ffma2(acc[0][1],a0,v0.y);
                ffma2(acc[0][2],a0,v1.x); ffma2(acc[0][3],a0,v1.y);
                ffma2(acc[1][0],a1,v0.x); ffma2(acc[1][1],a1,v0.y);
                ffma2(acc[1][2],a1,v1.x); ffma2(acc[1][3],a1,v1.y);
                ffma2(acc[2][0],a2,v0.x); ffma2(acc[2][1],a2,v0.y);
                ffma2(acc[2][2],a2,v1.x); ffma2(acc[2][3],a2,v1.y);
                ffma2(acc[3][0],a3,v0.x); ffma2(acc[3][1],a3,v0.y);
                ffma2(acc[3][2],a3,v1.x); ffma2(acc[3][3],a3,v1.y);
            }
            __syncthreads();
        }
        #pragma unroll
        for(int i=0;i<4;i++){
            int r=rg*4+i;
            float iv=1.f/sSum[r];
            float* dst=&ub[(size_t)(r>>2)*1024+(r&3)*128+cg];
            float2 f0=unp(acc[i][0]), f1=unp(acc[i][1]), f2=unp(acc[i][2]), f3=unp(acc[i][3]);
            *(float4*)dst    =make_float4(f0.x*iv,f0.y*iv,f1.x*iv,f1.y*iv);
            *(float4*)(dst+4)=make_float4(f2.x*iv,f2.y*iv,f3.x*iv,f3.y*iv);
        }
        __syncthreads();
    }
}

__global__ void __launch_bounds__(128) k_head2(const float* h,const float* w2,const float* b2,float* out){
    int b=blockIdx.x, c=threadIdx.x;
    float s=h[(size_t)b*DD+c]*w2[c];
    #pragma unroll
    for(int o=16;o;o>>=1) s+=__shfl_xor_sync(~0u,s,o);
    __shared__ float red[4];
    if((c&31)==0) red[c>>5]=s;
    __syncthreads();
    if(c==0){
        float t=red[0]+red[1]+red[2]+red[3]+b2[0];
        out[b]=fmaxf(t,0.f)+log1pf(__expf(-fabsf(t)));
    }
}

extern "C" void kernel_launch(void* const* d_in, const int* in_sizes, int n_in,
                              void* d_out, int out_size){
    (void)in_sizes;(void)n_in;(void)out_size;
    const float* drug_k=(const float*)d_in[0];
    const float* drug_v=(const float*)d_in[1];
    const float* enz_k =(const float*)d_in[2];
    const float* enz_v =(const float*)d_in[3];
    const int*   db    =(const int*)d_in[4];
    const int*   eb    =(const int*)d_in[5];
    const float* lat   =(const float*)d_in[6];
    const float* wq_d=(const float*)d_in[7];  const float* bq_d=(const float*)d_in[8];
    const float* wq_e=(const float*)d_in[9];  const float* bq_e=(const float*)d_in[10];
    const float* mw_d=(const float*)d_in[11]; const float* mb_d=(const float*)d_in[12];
    const float* ow_d=(const float*)d_in[13]; const float* ob_d=(const float*)d_in[14];
    const float* mw_e=(const float*)d_in[15]; const float* mb_e=(const float*)d_in[16];
    const float* ow_e=(const float*)d_in[17]; const float* ob_e=(const float*)d_in[18];
    const float* l1g=(const float*)d_in[19];  const float* l1b=(const float*)d_in[20];
    const float* l2g=(const float*)d_in[21];  const float* l2b=(const float*)d_in[22];
    const float* fw1=(const float*)d_in[23];  const float* fb1=(const float*)d_in[24];
    const float* fw2=(const float*)d_in[25];  const float* fb2=(const float*)d_in[26];
    const float* hw1=(const float*)d_in[27];  const float* hb1=(const float*)d_in[28];
    const float* hw2=(const float*)d_in[29];  const float* hb2=(const float*)d_in[30];
    float* out=(float*)d_out;

    static float *p_lat,*p_nl,*p_qp,*p_u,*p_ffh,*p_h,*p_Qt,*p_qb,*p_M,*p_mb; static int* p_ctr;
    static bool init=false;
    if(!init){
        cudaGetSymbolAddress((void**)&p_lat,g_lat); cudaGetSymbolAddress((void**)&p_nl,g_nl);
        cudaGetSymbolAddress((void**)&p_qp,g_qp);   cudaGetSymbolAddress((void**)&p_u,g_u);
        cudaGetSymbolAddress((void**)&p_ffh,g_ffh); cudaGetSymbolAddress((void**)&p_h,g_h);
        cudaGetSymbolAddress((void**)&p_Qt,g_Qt);   cudaGetSymbolAddress((void**)&p_qb,g_qb);
        cudaGetSymbolAddress((void**)&p_M,g_M);     cudaGetSymbolAddress((void**)&p_mb,g_mb);
        cudaGetSymbolAddress((void**)&p_ctr,g_ctr);
        cudaFuncSetAttribute(k_attn,cudaFuncAttributeMaxDynamicSharedMemorySize,60000);
        init=true;
    }
    k_starts<<<1,1024>>>(db,eb);
    k_pre<<<32,256>>>(mw_d,mb_d,ow_d,ob_d,mw_e,mb_e,ow_e,ob_e);
    k_pre2<<<64,256>>>(wq_d,bq_d,wq_e,bq_e);
    k_init<<<1024,256>>>(lat);

    const int smemA=(RR*DD+32*132+32*68)*4;  // 58368
    for(int l=0;l<NLAYER;l++){
        k_ln<<<1024,256>>>(p_lat,p_nl,l1g+l*DD,l1b+l*DD);
        // qp[8192][1024] = nl @ Qt^T + qb  (both modalities)
        k_gemm<false,false><<<dim3(128,16),256>>>(p_nl,DD,p_Qt+l*1024*DD,DD,p_qp,1024,p_qb+l*1024,DD);
        k_attn<<<444,256,smemA>>>(p_qp,drug_k,drug_v,enz_k,enz_v,p_u,p_ctr+l);
        // lat += u @ M^T + mb  (K=1024 covers both modalities)
        k_gemm<true,false><<<dim3(128,2),256>>>(p_u,1024,p_M+l*DD*1024,1024,p_lat,DD,p_mb+l*DD,1024);
        k_ln<<<1024,256>>>(p_lat,p_nl,l2g+l*DD,l2b+l*DD);
        k_gemm<false,true><<<dim3(128,4),256>>>(p_nl,DD,fw1+l*2*DD*DD,DD,p_ffh,2*DD,fb1+l*2*DD,DD);
        k_gemm<true,false><<<dim3(128,2),256>>>(p_ffh,2*DD,fw2+l*2*DD*DD,2*DD,p_lat,DD,fb2+l*DD,2*DD);
    }
    k_gemm<false,true><<<dim3(8,2),256>>>(p_lat,NLAT*DD,hw1,NLAT*DD,p_h,DD,hb1,NLAT*DD);
    k_head2<<<BB,128>>>(p_h,hw2,hb2,out);
}

// round 9
// speedup vs baseline: 1.6232x; 1.1618x over previous
#include <cuda_runtime.h>
#include <math.h>

#define BB 512
#define DD 128
#define NLAT 16
#define NLAYER 4
#define NDRUG 25600
#define NENZ 153600
#define RR 64

__device__ float g_lat[BB*NLAT*DD];
__device__ float g_nl [BB*NLAT*DD];
__device__ float g_qp [BB*NLAT*1024];   // [8192][1024] both modalities
__device__ float g_u  [BB*NLAT*1024];
__device__ float g_ffh[BB*NLAT*2*DD];
__device__ float g_h  [BB*DD];
__device__ float g_P  [8*DD*512];       // [l][m][cin 128][512]
__device__ float g_pb [8*512];
__device__ float g_Qt [4*1024*DD];      // [l][c 1024][k 128]
__device__ float g_qb [4*1024];
__device__ float g_M  [4*DD*1024];      // [l][c 128][k 1024]
__device__ float g_mb [4*DD];
__device__ int   g_st [2*(BB+1)];
__device__ int   g_ctr[4];

// ---- packed f32x2 helpers ----
typedef unsigned long long ull;
__device__ __forceinline__ void ffma2(ull &d, ull a, ull b){
    asm("fma.rn.f32x2 %0, %1, %2, %0;" : "+l"(d) : "l"(a), "l"(b));
}
__device__ __forceinline__ void mul2(ull &d, ull s){
    asm("mul.rn.f32x2 %0, %0, %1;" : "+l"(d) : "l"(s));
}
__device__ __forceinline__ ull dup2(float a){
    ull r; asm("mov.b64 %0, {%1,%1};" : "=l"(r) : "f"(a)); return r;
}
__device__ __forceinline__ float2 unp(ull v){
    float2 f; asm("mov.b64 {%0,%1}, %2;" : "=f"(f.x), "=f"(f.y) : "l"(v)); return f;
}

__device__ __forceinline__ int lowb(const int* a, int n, int v){
    int lo=0, hi=n;
    while(lo<hi){int mid=(lo+hi)>>1; if(a[mid]<v) lo=mid+1; else hi=mid;}
    return lo;
}

__global__ void k_starts(const int* db, const int* eb){
    int b=threadIdx.x;
    if(b<BB){ g_st[b]=lowb(db,NDRUG,b); g_st[BB+1+b]=lowb(eb,NENZ,b); }
    if(b==0){ g_st[BB]=NDRUG; g_st[2*BB+1]=NENZ; }
    if(b<4*DD) g_mb[b]=0.f;
    if(b<4) g_ctr[b]=0;
}

__global__ void k_init(const float* lat){
    int i=blockIdx.x*256+threadIdx.x;
    ((float4*)g_lat)[i]=((const float4*)lat)[i&511];
}

// per (l,m,h): P block (Wqm^T Wk /sqrt32), pb, M block (Wo Wv), mb
__global__ void k_pre(const float* mwd,const float* mbd,const float* owd,const float* obd,
                      const float* mwe,const float* mbe,const float* owe,const float* obe){
    int idx=blockIdx.x, l=idx>>3, m=(idx>>2)&1, h=idx&3;
    const float* w =(m?mwe:mwd)+l*3*DD*DD;
    const float* b3=(m?mbe:mbd)+l*3*DD;
    const float* ow=(m?owe:owd)+l*DD*DD;
    const float* ob=(m?obe:obd)+l*DD;
    float* P =g_P +(l*2+m)*DD*512;
    float* pb=g_pb+(l*2+m)*512;
    __shared__ float sA[32*128], sB[32*128];
    int tid=threadIdx.x;
    const float inv=0.17677669529663687f;
    for(int i=tid;i<32*128;i+=256){int j=i>>7,c=i&127;
        sA[i]=w[(h*32+j)*DD+c]; sB[i]=w[(DD+h*32+j)*DD+c];}
    __syncthreads();
    for(int e=tid;e<128*128;e+=256){int c=e>>7,d=e&127; float s=0.f;
        #pragma unroll
        for(int j=0;j<32;j++) s+=sA[j*128+c]*sB[j*128+d];
        P[c*512+h*128+d]=s*inv;}
    if(tid<128){float s=0.f;
        for(int j=0;j<32;j++) s+=b3[h*32+j]*sB[j*128+tid];
        pb[h*128+tid]=s*inv;}
    __syncthreads();
    for(int i=tid;i<32*128;i+=256){int j=i>>7,c=i&127; sB[i]=w[(2*DD+h*32+j)*DD+c];}
    for(int i=tid;i<128*32;i+=256){int c=i>>5,j=i&31; sA[c*32+j]=ow[c*DD+h*32+j];}
    __syncthreads();
    for(int e=tid;e<128*128;e+=256){int c=e>>7,d=e&127; float s=0.f;
        #pragma unroll
        for(int j=0;j<32;j++) s+=sA[c*32+j]*sB[j*128+d];
        g_M[(l*DD+c)*1024 + m*512 + h*128 + d]=s;}
    if(tid<128){float s=(m==0&&h==0)?ob[tid]:0.f;
        for(int j=0;j<32;j++) s+=sA[tid*32+j]*b3[2*DD+h*32+j];
        atomicAdd(&g_mb[l*DD+tid],s);}
}

// Qt[l][c][k] = sum_j wq[m][j][k] * P[l][m][j][c512]; qb = bq@P + pb
__global__ void k_pre2(const float* wqd,const float* bqd,const float* wqe,const float* bqe){
    int idx=blockIdx.x, l=idx>>4, m=(idx>>3)&1, cb=idx&7;
    const float* wq=(m?wqe:wqd)+l*DD*DD;
    const float* bq=(m?bqe:bqd)+l*DD;
    const float* P =g_P +(l*2+m)*DD*512;
    __shared__ float sP[128*64];
    int tid=threadIdx.x;
    for(int i=tid;i<128*64;i+=256){int j=i>>6,cc=i&63; sP[j*64+cc]=P[j*512+cb*64+cc];}
    __syncthreads();
    for(int e=tid;e<64*128;e+=256){
        int cc=e>>7, k=e&127;
        float s=0.f;
        #pragma unroll 8
        for(int j=0;j<128;j++) s+=wq[j*DD+k]*sP[j*64+cc];
        g_Qt[(l*1024 + m*512 + cb*64 + cc)*DD + k]=s;
    }
    if(tid<64){
        float s=g_pb[(l*2+m)*512 + cb*64 + tid];
        for(int j=0;j<128;j++) s+=bq[j]*sP[j*64+tid];
        g_qb[l*1024 + m*512 + cb*64 + tid]=s;
    }
}

// layernorm: 1 warp per 128-d row
__global__ void __launch_bounds__(256) k_ln(const float* x,float* y,const float* g,const float* bb){
    int row=blockIdx.x*8+(threadIdx.x>>5), lane=threadIdx.x&31;
    float4 v=*(const float4*)(x+(size_t)row*DD+lane*4);
    float s=v.x+v.y+v.z+v.w, s2=v.x*v.x+v.y*v.y+v.z*v.z+v.w*v.w;
    #pragma unroll
    for(int o=16;o;o>>=1){s+=__shfl_xor_sync(~0u,s,o); s2+=__shfl_xor_sync(~0u,s2,o);}
    float m=s*(1.f/128.f), var=s2*(1.f/128.f)-m*m, iv=rsqrtf(var+1e-5f);
    float4 gg=*(const float4*)(g+lane*4), b4=*(const float4*)(bb+lane*4);
    float4 o;
    o.x=(v.x-m)*iv*gg.x+b4.x; o.y=(v.y-m)*iv*gg.y+b4.y;
    o.z=(v.z-m)*iv*gg.z+b4.z; o.w=(v.w-m)*iv*gg.w+b4.w;
    *(float4*)(y+(size_t)row*DD+lane*4)=o;
}

// GEMM, FFMA2 lanes paired over k, conflict-free interleaved fragment mapping.
template<bool ACC,bool RELU>
__global__ void __launch_bounds__(256) k_gemm(const float* A,int lda,const float* W,int ldw,
                                              float* C,int ldc,const float* bias,int K){
    __shared__ float sA[64*36], sB[64*36];
    int rb=blockIdx.x*64, cb=blockIdx.y*64, tid=threadIdx.x;
    int tx=tid&15, ty=tid>>4;
    ull acc2[4][4]={};
    for(int k0=0;k0<K;k0+=32){
        #pragma unroll
        for(int it=0;it<2;it++){
            int i=tid+it*256, row=i>>3, k4=(i&7)<<2;
            *(float4*)&sA[row*36+k4]=*(const float4*)(A+(size_t)(rb+row)*lda+k0+k4);
            *(float4*)&sB[row*36+k4]=*(const float4*)(W+(size_t)(cb+row)*ldw+k0+k4);
        }
        __syncthreads();
        #pragma unroll
        for(int kq=0;kq<32;kq+=4){
            ulonglong2 a[4], b[4];
            #pragma unroll
            for(int j=0;j<4;j++){
                a[j]=*(ulonglong2*)&sA[(ty+16*j)*36+kq];
                b[j]=*(ulonglong2*)&sB[(tx+16*j)*36+kq];
            }
            #pragma unroll
            for(int i=0;i<4;i++)
                #pragma unroll
                for(int j=0;j<4;j++){
                    ffma2(acc2[i][j],a[i].x,b[j].x);
                    ffma2(acc2[i][j],a[i].y,b[j].y);
                }
        }
        __syncthreads();
    }
    #pragma unroll
    for(int i=0;i<4;i++){
        int r=rb+ty+16*i;
        #pragma unroll
        for(int j=0;j<4;j++){
            int c=cb+tx+16*j;
            float2 f=unp(acc2[i][j]);
            float v=f.x+f.y+bias[c];
            if(ACC) v+=C[(size_t)r*ldc+c];
            if(RELU) v=fmaxf(v,0.f);
            C[(size_t)r*ldc+c]=v;
        }
    }
}

// persistent flash attention, conflict-free smem mappings
__global__ void __launch_bounds__(256) k_attn(const float* qp,
                                              const float* kd,const float* vd,
                                              const float* ke,const float* ve,
                                              float* u,int* ctr){
    extern __shared__ float sm[];
    float* sQ=sm;              // [64][128]
    float* sKV=sm+RR*DD;       // [32][132]
    float* sS=sKV+32*132;      // [32 tok][68]  (transposed scores)
    __shared__ float sM[RR], sSum[RR], sScale[RR];
    __shared__ int sItem;
    int tid=threadIdx.x;
    int ty=tid>>4, tx=tid&15;
    int rg=tid>>4;
    int c0=tx*4, c1=64+tx*4;   // conflict-free V column groups
    int w=tid>>5, lane=tid&31;

    for(;;){
        if(tid==0) sItem=atomicAdd(ctr,1);
        __syncthreads();
        int item=sItem;
        if(item>=1024) break;
        int isE=item<512;              // enzyme first (longer)
        int b=item&511;
        int mcol=isE?512:0;
        const float* kb=isE?ke:kd;
        const float* vb=isE?ve:vd;
        const int* st=g_st+(isE?(BB+1):0);
        int maxLen=isE?512:128;
        int s0=st[b], len=st[b+1]-s0;
        if(len>maxLen) len=maxLen;
        const float* qpb=qp+(size_t)b*NLAT*1024+mcol;
        float* ub=u+(size_t)b*NLAT*1024+mcol;

        if(len==0){
            for(int i=tid;i<RR*DD/4;i+=256){
                int r=i>>5, c4=(i&31)<<2;
                *(float4*)&ub[(size_t)(r>>2)*1024+(r&3)*128+c4]=make_float4(0.f,0.f,0.f,0.f);
            }
            __syncthreads();
            continue;
        }
        for(int i=tid;i<RR*DD/4;i+=256){
            int r=i>>5, c4=(i&31)<<2;
            *(float4*)&sQ[r*DD+c4]=*(const float4*)(qpb+(size_t)(r>>2)*1024+(r&3)*128+c4);
        }
        if(tid<RR){ sM[tid]=-1e30f; sSum[tid]=0.f; }
        __syncthreads();

        ull acc[4][4]={};
        for(int t0=0;t0<len;t0+=32){
            int tc=min(32,len-t0);
            for(int i=tid;i<tc*32;i+=256){
                int row=i>>5, c4=(i&31)<<2;
                *(float4*)&sKV[row*132+c4]=*(const float4*)(kb+(size_t)(s0+t0+row)*DD+c4);
            }
            __syncthreads();
            { // scores for tokens tx and tx+16 (conflict-free: 132*tx ≡ 4tx mod 32)
                ull sc2[4][2]={};
                #pragma unroll 8
                for(int d=0;d<DD;d+=4){
                    ulonglong2 k0=*(ulonglong2*)&sKV[tx*132+d];
                    ulonglong2 k1=*(ulonglong2*)&sKV[(tx+16)*132+d];
                    #pragma unroll
                    for(int i=0;i<4;i++){
                        ulonglong2 q2=*(ulonglong2*)&sQ[(ty*4+i)*DD+d];
                        ffma2(sc2[i][0],q2.x,k0.x); ffma2(sc2[i][0],q2.y,k0.y);
                        ffma2(sc2[i][1],q2.x,k1.x); ffma2(sc2[i][1],q2.y,k1.y);
                    }
                }
                #pragma unroll
                for(int i=0;i<4;i++){
                    float2 fa=unp(sc2[i][0]), fb2=unp(sc2[i][1]);
                    sS[tx*68+ty*4+i]     =(tx<tc)?(fa.x+fa.y):-1e30f;
                    sS[(tx+16)*68+ty*4+i]=(tx+16<tc)?(fb2.x+fb2.y):-1e30f;
                }
            }
            __syncthreads();
            // online softmax (8 warps x 8 rows)
            for(int r=w;r<RR;r+=8){
                float x=sS[lane*68+r];
                float tm=x;
                #pragma unroll
                for(int o=16;o;o>>=1) tm=fmaxf(tm,__shfl_xor_sync(~0u,tm,o));
                float mOld=sM[r], mNew=fmaxf(mOld,tm);
                float e=__expf(x-mNew);
                float ts=e;
                #pragma unroll
                for(int o=16;o;o>>=1) ts+=__shfl_xor_sync(~0u,ts,o);
                sS[lane*68+r]=e;
                if(lane==0){
                    float sc=__expf(mOld-mNew);
                    sScale[r]=sc;
                    sSum[r]=sSum[r]*sc+ts;
                    sM[r]=mNew;
                }
            }
            // load V into same buffer
            for(int i=tid;i<tc*32;i+=256){
                int row=i>>5, c4=(i&31)<<2;
                *(float4*)&sKV[row*132+c4]=*(const float4*)(vb+(size_t)(s0+t0+row)*DD+c4);
            }
            __syncthreads();
            #pragma unroll
            for(int i=0;i<4;i++){
                ull sc2=dup2(sScale[rg*4+i]);
                #pragma unroll
                for(int p=0;p<4;p++) mul2(acc[i][p],sc2);
            }
            for(int t=0;t<tc;t++){
                ulonglong2 v0=*(ulonglong2*)&sKV[t*132+c0];  // 4tx mod 32: conflict-free
                ulonglong2 v1=*(ulonglong2*)&sKV[t*132+c1];
                float4 s4=*(float4*)&sS[t*68+rg*4];          // half-warp broadcast
                ull a0=dup2(s4.x), a1=dup2(s4.y), a2=dup2(s4.z), a3=dup2(s4.w);
                ffma2(acc[0][0],a0,v0.x); ffma2(acc[0][1],a0,v0.y);
                ffma2(acc[0][2],a0,v1.x); ffma2(acc[0][3],a0,v1.y);
                ffma2(acc[1][0],a1,v0.x); ffma2(acc[1][1],a1,v0.y);
                ffma2(acc[1][2],a1,v1.x); ffma2(acc[1][3],a1,v1.y);
                ffma2(acc[2][0],a2,v0.x); ffma2(acc[2][1],a2,v0.y);
                ffma2(acc[2][2],a2,v1.x); ffma2(acc[2][3],a2,v1.y);
                ffma2(acc[3][0],a3,v0.x); ffma2(acc[3][1],a3,v0.y);
                ffma2(acc[3][2],a3,v1.x); ffma2(acc[3][3],a3,v1.y);
            }
            __syncthreads();
        }
        #pragma unroll
        for(int i=0;i<4;i++){
            int r=rg*4+i;
            float iv=1.f/sSum[r];
            float* base=&ub[(size_t)(r>>2)*1024+(r&3)*128];
            float2 f0=unp(acc[i][0]), f1=unp(acc[i][1]), f2=unp(acc[i][2]), f3=unp(acc[i][3]);
            *(float4*)(base+c0)=make_float4(f0.x*iv,f0.y*iv,f1.x*iv,f1.y*iv);
            *(float4*)(base+c1)=make_float4(f2.x*iv,f2.y*iv,f3.x*iv,f3.y*iv);
        }
        __syncthreads();
    }
}

__global__ void __launch_bounds__(128) k_head2(const float* h,const float* w2,const float* b2,float* out){
    int b=blockIdx.x, c=threadIdx.x;
    float s=h[(size_t)b*DD+c]*w2[c];
    #pragma unroll
    for(int o=16;o;o>>=1) s+=__shfl_xor_sync(~0u,s,o);
    __shared__ float red[4];
    if((c&31)==0) red[c>>5]=s;
    __syncthreads();
    if(c==0){
        float t=red[0]+red[1]+red[2]+red[3]+b2[0];
        out[b]=fmaxf(t,0.f)+log1pf(__expf(-fabsf(t)));
    }
}

extern "C" void kernel_launch(void* const* d_in, const int* in_sizes, int n_in,
                              void* d_out, int out_size){
    (void)in_sizes;(void)n_in;(void)out_size;
    const float* drug_k=(const float*)d_in[0];
    const float* drug_v=(const float*)d_in[1];
    const float* enz_k =(const float*)d_in[2];
    const float* enz_v =(const float*)d_in[3];
    const int*   db    =(const int*)d_in[4];
    const int*   eb    =(const int*)d_in[5];
    const float* lat   =(const float*)d_in[6];
    const float* wq_d=(const float*)d_in[7];  const float* bq_d=(const float*)d_in[8];
    const float* wq_e=(const float*)d_in[9];  const float* bq_e=(const float*)d_in[10];
    const float* mw_d=(const float*)d_in[11]; const float* mb_d=(const float*)d_in[12];
    const float* ow_d=(const float*)d_in[13]; const float* ob_d=(const float*)d_in[14];
    const float* mw_e=(const float*)d_in[15]; const float* mb_e=(const float*)d_in[16];
    const float* ow_e=(const float*)d_in[17]; const float* ob_e=(const float*)d_in[18];
    const float* l1g=(const float*)d_in[19];  const float* l1b=(const float*)d_in[20];
    const float* l2g=(const float*)d_in[21];  const float* l2b=(const float*)d_in[22];
    const float* fw1=(const float*)d_in[23];  const float* fb1=(const float*)d_in[24];
    const float* fw2=(const float*)d_in[25];  const float* fb2=(const float*)d_in[26];
    const float* hw1=(const float*)d_in[27];  const float* hb1=(const float*)d_in[28];
    const float* hw2=(const float*)d_in[29];  const float* hb2=(const float*)d_in[30];
    float* out=(float*)d_out;

    static float *p_lat,*p_nl,*p_qp,*p_u,*p_ffh,*p_h,*p_Qt,*p_qb,*p_M,*p_mb; static int* p_ctr;
    static bool init=false;
    if(!init){
        cudaGetSymbolAddress((void**)&p_lat,g_lat); cudaGetSymbolAddress((void**)&p_nl,g_nl);
        cudaGetSymbolAddress((void**)&p_qp,g_qp);   cudaGetSymbolAddress((void**)&p_u,g_u);
        cudaGetSymbolAddress((void**)&p_ffh,g_ffh); cudaGetSymbolAddress((void**)&p_h,g_h);
        cudaGetSymbolAddress((void**)&p_Qt,g_Qt);   cudaGetSymbolAddress((void**)&p_qb,g_qb);
        cudaGetSymbolAddress((void**)&p_M,g_M);     cudaGetSymbolAddress((void**)&p_mb,g_mb);
        cudaGetSymbolAddress((void**)&p_ctr,g_ctr);
        cudaFuncSetAttribute(k_attn,cudaFuncAttributeMaxDynamicSharedMemorySize,60000);
        init=true;
    }
    k_starts<<<1,1024>>>(db,eb);
    k_pre<<<32,256>>>(mw_d,mb_d,ow_d,ob_d,mw_e,mb_e,ow_e,ob_e);
    k_pre2<<<64,256>>>(wq_d,bq_d,wq_e,bq_e);
    k_init<<<1024,256>>>(lat);

    const int smemA=(RR*DD+32*132+32*68)*4;  // 58368
    for(int l=0;l<NLAYER;l++){
        k_ln<<<1024,256>>>(p_lat,p_nl,l1g+l*DD,l1b+l*DD);
        k_gemm<false,false><<<dim3(128,16),256>>>(p_nl,DD,p_Qt+l*1024*DD,DD,p_qp,1024,p_qb+l*1024,DD);
        k_attn<<<444,256,smemA>>>(p_qp,drug_k,drug_v,enz_k,enz_v,p_u,p_ctr+l);
        k_gemm<true,false><<<dim3(128,2),256>>>(p_u,1024,p_M+l*DD*1024,1024,p_lat,DD,p_mb+l*DD,1024);
        k_ln<<<1024,256>>>(p_lat,p_nl,l2g+l*DD,l2b+l*DD);
        k_gemm<false,true><<<dim3(128,4),256>>>(p_nl,DD,fw1+l*2*DD*DD,DD,p_ffh,2*DD,fb1+l*2*DD,DD);
        k_gemm<true,false><<<dim3(128,2),256>>>(p_ffh,2*DD,fw2+l*2*DD*DD,2*DD,p_lat,DD,fb2+l*DD,2*DD);
    }
    k_gemm<false,true><<<dim3(8,2),256>>>(p_lat,NLAT*DD,hw1,NLAT*DD,p_h,DD,hb1,NLAT*DD);
    k_head2<<<BB,128>>>(p_h,hw2,hb2,out);
}

// round 11
// speedup vs baseline: 1.8045x; 1.1117x over previous
#include <cuda_runtime.h>
#include <math.h>

#define BB 512
#define DD 128
#define NLAT 16
#define NLAYER 4
#define NDRUG 25600
#define NENZ 153600
#define RR 64

__device__ float g_lat[BB*NLAT*DD];
__device__ float g_nl [BB*NLAT*DD];
__device__ float g_qp [BB*NLAT*1024];   // [8192][1024] both modalities
__device__ float g_u  [BB*NLAT*1024];
__device__ float g_ffh[BB*NLAT*2*DD];
__device__ float g_h  [BB*DD];
__device__ float g_P  [8*DD*512];       // [l][m][cin 128][512]
__device__ float g_pb [8*512];
__device__ float g_Qt [4*1024*DD];      // [l][c 1024][k 128]
__device__ float g_qb [4*1024];
__device__ float g_M  [4*DD*1024];      // [l][c 128][k 1024]
__device__ float g_mb [4*DD];
__device__ int   g_st [2*(BB+1)];
__device__ int   g_ctr[4];

// ---- packed f32x2 helpers ----
typedef unsigned long long ull;
__device__ __forceinline__ void ffma2(ull &d, ull a, ull b){
    asm("fma.rn.f32x2 %0, %1, %2, %0;" : "+l"(d) : "l"(a), "l"(b));
}
__device__ __forceinline__ void mul2(ull &d, ull s){
    asm("mul.rn.f32x2 %0, %0, %1;" : "+l"(d) : "l"(s));
}
__device__ __forceinline__ ull dup2(float a){
    ull r; asm("mov.b64 %0, {%1,%1};" : "=l"(r) : "f"(a)); return r;
}
__device__ __forceinline__ float2 unp(ull v){
    float2 f; asm("mov.b64 {%0,%1}, %2;" : "=f"(f.x), "=f"(f.y) : "l"(v)); return f;
}

__device__ __forceinline__ int lowb(const int* a, int n, int v){
    int lo=0, hi=n;
    while(lo<hi){int mid=(lo+hi)>>1; if(a[mid]<v) lo=mid+1; else hi=mid;}
    return lo;
}

__global__ void k_starts(const int* db, const int* eb){
    int b=threadIdx.x;
    if(b<BB){ g_st[b]=lowb(db,NDRUG,b); g_st[BB+1+b]=lowb(eb,NENZ,b); }
    if(b==0){ g_st[BB]=NDRUG; g_st[2*BB+1]=NENZ; }
    if(b<4*DD) g_mb[b]=0.f;
    if(b<4) g_ctr[b]=0;
}

__global__ void k_init(const float* lat){
    int i=blockIdx.x*256+threadIdx.x;
    ((float4*)g_lat)[i]=((const float4*)lat)[i&511];
}

// per (l,m,h): P block (Wqm^T Wk /sqrt32), pb, M block (Wo Wv), mb
__global__ void k_pre(const float* mwd,const float* mbd,const float* owd,const float* obd,
                      const float* mwe,const float* mbe,const float* owe,const float* obe){
    int idx=blockIdx.x, l=idx>>3, m=(idx>>2)&1, h=idx&3;
    const float* w =(m?mwe:mwd)+l*3*DD*DD;
    const float* b3=(m?mbe:mbd)+l*3*DD;
    const float* ow=(m?owe:owd)+l*DD*DD;
    const float* ob=(m?obe:obd)+l*DD;
    float* P =g_P +(l*2+m)*DD*512;
    float* pb=g_pb+(l*2+m)*512;
    __shared__ float sA[32*128], sB[32*128];
    int tid=threadIdx.x;
    const float inv=0.17677669529663687f;
    for(int i=tid;i<32*128;i+=256){int j=i>>7,c=i&127;
        sA[i]=w[(h*32+j)*DD+c]; sB[i]=w[(DD+h*32+j)*DD+c];}
    __syncthreads();
    for(int e=tid;e<128*128;e+=256){int c=e>>7,d=e&127; float s=0.f;
        #pragma unroll
        for(int j=0;j<32;j++) s+=sA[j*128+c]*sB[j*128+d];
        P[c*512+h*128+d]=s*inv;}
    if(tid<128){float s=0.f;
        for(int j=0;j<32;j++) s+=b3[h*32+j]*sB[j*128+tid];
        pb[h*128+tid]=s*inv;}
    __syncthreads();
    for(int i=tid;i<32*128;i+=256){int j=i>>7,c=i&127; sB[i]=w[(2*DD+h*32+j)*DD+c];}
    for(int i=tid;i<128*32;i+=256){int c=i>>5,j=i&31; sA[c*32+j]=ow[c*DD+h*32+j];}
    __syncthreads();
    for(int e=tid;e<128*128;e+=256){int c=e>>7,d=e&127; float s=0.f;
        #pragma unroll
        for(int j=0;j<32;j++) s+=sA[c*32+j]*sB[j*128+d];
        g_M[(l*DD+c)*1024 + m*512 + h*128 + d]=s;}
    if(tid<128){float s=(m==0&&h==0)?ob[tid]:0.f;
        for(int j=0;j<32;j++) s+=sA[tid*32+j]*b3[2*DD+h*32+j];
        atomicAdd(&g_mb[l*DD+tid],s);}
}

// Qt[l][c][k] = sum_j wq[m][j][k] * P[l][m][j][c512]; qb = bq@P + pb
__global__ void k_pre2(const float* wqd,const float* bqd,const float* wqe,const float* bqe){
    int idx=blockIdx.x, l=idx>>4, m=(idx>>3)&1, cb=idx&7;
    const float* wq=(m?wqe:wqd)+l*DD*DD;
    const float* bq=(m?bqe:bqd)+l*DD;
    const float* P =g_P +(l*2+m)*DD*512;
    __shared__ float sP[128*64];
    int tid=threadIdx.x;
    for(int i=tid;i<128*64;i+=256){int j=i>>6,cc=i&63; sP[j*64+cc]=P[j*512+cb*64+cc];}
    __syncthreads();
    for(int e=tid;e<64*128;e+=256){
        int cc=e>>7, k=e&127;
        float s=0.f;
        #pragma unroll 8
        for(int j=0;j<128;j++) s+=wq[j*DD+k]*sP[j*64+cc];
        g_Qt[(l*1024 + m*512 + cb*64 + cc)*DD + k]=s;
    }
    if(tid<64){
        float s=g_pb[(l*2+m)*512 + cb*64 + tid];
        for(int j=0;j<128;j++) s+=bq[j]*sP[j*64+tid];
        g_qb[l*1024 + m*512 + cb*64 + tid]=s;
    }
}

// layernorm: 1 warp per 128-d row
__global__ void __launch_bounds__(256) k_ln(const float* x,float* y,const float* g,const float* bb){
    int row=blockIdx.x*8+(threadIdx.x>>5), lane=threadIdx.x&31;
    float4 v=*(const float4*)(x+(size_t)row*DD+lane*4);
    float s=v.x+v.y+v.z+v.w, s2=v.x*v.x+v.y*v.y+v.z*v.z+v.w*v.w;
    #pragma unroll
    for(int o=16;o;o>>=1){s+=__shfl_xor_sync(~0u,s,o); s2+=__shfl_xor_sync(~0u,s2,o);}
    float m=s*(1.f/128.f), var=s2*(1.f/128.f)-m*m, iv=rsqrtf(var+1e-5f);
    float4 gg=*(const float4*)(g+lane*4), b4=*(const float4*)(bb+lane*4);
    float4 o;
    o.x=(v.x-m)*iv*gg.x+b4.x; o.y=(v.y-m)*iv*gg.y+b4.y;
    o.z=(v.z-m)*iv*gg.z+b4.z; o.w=(v.w-m)*iv*gg.w+b4.w;
    *(float4*)(y+(size_t)row*DD+lane*4)=o;
}

// GEMM, FFMA2 lanes paired over k, conflict-free interleaved fragment mapping.
template<bool ACC,bool RELU>
__global__ void __launch_bounds__(256) k_gemm(const float* A,int lda,const float* W,int ldw,
                                              float* C,int ldc,const float* bias,int K){
    __shared__ float sA[64*36], sB[64*36];
    int rb=blockIdx.x*64, cb=blockIdx.y*64, tid=threadIdx.x;
    int tx=tid&15, ty=tid>>4;
    ull acc2[4][4]={};
    for(int k0=0;k0<K;k0+=32){
        #pragma unroll
        for(int it=0;it<2;it++){
            int i=tid+it*256, row=i>>3, k4=(i&7)<<2;
            *(float4*)&sA[row*36+k4]=*(const float4*)(A+(size_t)(rb+row)*lda+k0+k4);
            *(float4*)&sB[row*36+k4]=*(const float4*)(W+(size_t)(cb+row)*ldw+k0+k4);
        }
        __syncthreads();
        #pragma unroll
        for(int kq=0;kq<32;kq+=4){
            ulonglong2 a[4], b[4];
            #pragma unroll
            for(int j=0;j<4;j++){
                a[j]=*(ulonglong2*)&sA[(ty+16*j)*36+kq];
                b[j]=*(ulonglong2*)&sB[(tx+16*j)*36+kq];
            }
            #pragma unroll
            for(int i=0;i<4;i++)
                #pragma unroll
                for(int j=0;j<4;j++){
                    ffma2(acc2[i][j],a[i].x,b[j].x);
                    ffma2(acc2[i][j],a[i].y,b[j].y);
                }
        }
        __syncthreads();
    }
    #pragma unroll
    for(int i=0;i<4;i++){
        int r=rb+ty+16*i;
        #pragma unroll
        for(int j=0;j<4;j++){
            int c=cb+tx+16*j;
            float2 f=unp(acc2[i][j]);
            float v=f.x+f.y+bias[c];
            if(ACC) v+=C[(size_t)r*ldc+c];
            if(RELU) v=fmaxf(v,0.f);
            C[(size_t)r*ldc+c]=v;
        }
    }
}

// persistent flash attention: register-resident softmax state, double-buffered K+V,
// 2 barriers/tile. Rows ty*4+i are produced & consumed within one half-warp.
__global__ void __launch_bounds__(256) k_attn(const float* qp,
                                              const float* kd,const float* vd,
                                              const float* ke,const float* ve,
                                              float* u,int* ctr){
    extern __shared__ float sm[];
    float* sQ=sm;               // [64][128]
    float* sK=sm+RR*DD;         // [32][132]
    float* sV=sK+32*132;        // [32][132]
    float* sS=sV+32*132;        // [32 tok][68] transposed exp-scores (warp-local)
    __shared__ int sItem;
    int tid=threadIdx.x;
    int ty=tid>>4, tx=tid&15;
    int c0=tx*4, c1=64+tx*4;    // conflict-free V column groups

    float4 rK[4], rV[4];
    #pragma unroll
    for(int it=0;it<4;it++){ rK[it]=make_float4(0.f,0.f,0.f,0.f); rV[it]=rK[it]; }

    for(;;){
        if(tid==0) sItem=atomicAdd(ctr,1);
        __syncthreads();
        int item=sItem;
        if(item>=1024) break;
        int isE=item<512;              // enzyme first (longer)
        int b=item&511;
        int mcol=isE?512:0;
        const float* kb=isE?ke:kd;
        const float* vb=isE?ve:vd;
        const int* st=g_st+(isE?(BB+1):0);
        int maxLen=isE?512:128;
        int s0=st[b], len=st[b+1]-s0;
        if(len>maxLen) len=maxLen;
        const float* qpb=qp+(size_t)b*NLAT*1024+mcol;
        float* ub=u+(size_t)b*NLAT*1024+mcol;

        if(len==0){
            for(int i=tid;i<RR*DD/4;i+=256){
                int r=i>>5, c4=(i&31)<<2;
                *(float4*)&ub[(size_t)(r>>2)*1024+(r&3)*128+c4]=make_float4(0.f,0.f,0.f,0.f);
            }
            __syncthreads();
            continue;
        }
        // load Q (smem stores protected by the sItem barrier above and the
        // first in-loop barrier below)
        for(int i=tid;i<RR*DD/4;i+=256){
            int r=i>>5, c4=(i&31)<<2;
            *(float4*)&sQ[r*DD+c4]=*(const float4*)(qpb+(size_t)(r>>2)*1024+(r&3)*128+c4);
        }
        // stage tile 0 into registers
        #pragma unroll
        for(int it=0;it<4;it++){
            int i=tid+it*256, row=i>>5, c4=(i&31)<<2;
            if(row<len){
                rK[it]=*(const float4*)(kb+(size_t)(s0+row)*DD+c4);
                rV[it]=*(const float4*)(vb+(size_t)(s0+row)*DD+c4);
            }
        }

        ull acc[4][4]={};
        float mrow[4], srow[4];
        #pragma unroll
        for(int i=0;i<4;i++){ mrow[i]=-1e30f; srow[i]=0.f; }

        for(int t0=0;t0<len;t0+=32){
            int tc=min(32,len-t0);
            __syncthreads();   // prior V-phase done reading sK/sV (and sQ ready on tile 0)
            #pragma unroll
            for(int it=0;it<4;it++){
                int i=tid+it*256, row=i>>5, c4=(i&31)<<2;
                *(float4*)&sK[row*132+c4]=rK[it];
                *(float4*)&sV[row*132+c4]=rV[it];
            }
            __syncthreads();   // tile visible
            // prefetch next tile while computing
            if(t0+32<len){
                #pragma unroll
                for(int it=0;it<4;it++){
                    int i=tid+it*256, row=i>>5, c4=(i&31)<<2;
                    if(t0+32+row<len){
                        rK[it]=*(const float4*)(kb+(size_t)(s0+t0+32+row)*DD+c4);
                        rV[it]=*(const float4*)(vb+(size_t)(s0+t0+32+row)*DD+c4);
                    }
                }
            }
            // scores for tokens tx and tx+16 (conflict-free: 132*tx ≡ 4tx mod 32)
            ull sc2[4][2]={};
            #pragma unroll 8
            for(int d=0;d<DD;d+=4){
                ulonglong2 k0=*(ulonglong2*)&sK[tx*132+d];
                ulonglong2 k1=*(ulonglong2*)&sK[(tx+16)*132+d];
                #pragma unroll
                for(int i=0;i<4;i++){
                    ulonglong2 q2=*(ulonglong2*)&sQ[(ty*4+i)*DD+d];
                    ffma2(sc2[i][0],q2.x,k0.x); ffma2(sc2[i][0],q2.y,k0.y);
                    ffma2(sc2[i][1],q2.x,k1.x); ffma2(sc2[i][1],q2.y,k1.y);
                }
            }
            // fused online softmax in registers (half-warp reductions, width 16)
            float scl[4];
            #pragma unroll
            for(int i=0;i<4;i++){
                int r=ty*4+i;
                float2 fa=unp(sc2[i][0]), fb=unp(sc2[i][1]);
                float sA0=(tx<tc)?(fa.x+fa.y):-1e30f;
                float sB0=(tx+16<tc)?(fb.x+fb.y):-1e30f;
                float tm=fmaxf(sA0,sB0);
                #pragma unroll
                for(int o=8;o;o>>=1) tm=fmaxf(tm,__shfl_xor_sync(~0u,tm,o));
                float mNew=fmaxf(mrow[i],tm);
                float e0=__expf(sA0-mNew), e1=__expf(sB0-mNew);
                float ts=e0+e1;
                #pragma unroll
                for(int o=8;o;o>>=1) ts+=__shfl_xor_sync(~0u,ts,o);
                scl[i]=__expf(mrow[i]-mNew);
                srow[i]=srow[i]*scl[i]+ts;
                mrow[i]=mNew;
                sS[tx*68+r]=e0;
                sS[(tx+16)*68+r]=e1;
            }
            __syncwarp();      // sS is produced & consumed within this warp
            // rescale accumulator, add exp-weighted V
            #pragma unroll
            for(int i=0;i<4;i++){
                ull s2=dup2(scl[i]);
                #pragma unroll
                for(int p=0;p<4;p++) mul2(acc[i][p],s2);
            }
            for(int t=0;t<tc;t++){
                ulonglong2 v0=*(ulonglong2*)&sV[t*132+c0];
                ulonglong2 v1=*(ulonglong2*)&sV[t*132+c1];
                float4 s4=*(float4*)&sS[t*68+ty*4];
                ull a0=dup2(s4.x), a1=dup2(s4.y), a2=dup2(s4.z), a3=dup2(s4.w);
                ffma2(acc[0][0],a0,v0.x); ffma2(acc[0][1],a0,v0.y);
                ffma2(acc[0][2],a0,v1.x); ffma2(acc[0][3],a0,v1.y);
                ffma2(acc[1][0],a1,v0.x); ffma2(acc[1][1],a1,v0.y);
                ffma2(acc[1][2],a1,v1.x); ffma2(acc[1][3],a1,v1.y);
                ffma2(acc[2][0],a2,v0.x); ffma2(acc[2][1],a2,v0.y);
                ffma2(acc[2][2],a2,v1.x); ffma2(acc[2][3],a2,v1.y);
                ffma2(acc[3][0],a3,v0.x); ffma2(acc[3][1],a3,v0.y);
                ffma2(acc[3][2],a3,v1.x); ffma2(acc[3][3],a3,v1.y);
            }
        }
        #pragma unroll
        for(int i=0;i<4;i++){
            int r=ty*4+i;
            float iv=1.f/srow[i];
            float* base=&ub[(size_t)(r>>2)*1024+(r&3)*128];
            float2 f0=unp(acc[i][0]), f1=unp(acc[i][1]), f2=unp(acc[i][2]), f3=unp(acc[i][3]);
            *(float4*)(base+c0)=make_float4(f0.x*iv,f0.y*iv,f1.x*iv,f1.y*iv);
            *(float4*)(base+c1)=make_float4(f2.x*iv,f2.y*iv,f3.x*iv,f3.y*iv);
        }
        __syncthreads();   // all reads of sQ/sK/sV done before next item's writes
    }
}

__global__ void __launch_bounds__(128) k_head2(const float* h,const float* w2,const float* b2,float* out){
    int b=blockIdx.x, c=threadIdx.x;
    float s=h[(size_t)b*DD+c]*w2[c];
    #pragma unroll
    for(int o=16;o;o>>=1) s+=__shfl_xor_sync(~0u,s,o);
    __shared__ float red[4];
    if((c&31)==0) red[c>>5]=s;
    __syncthreads();
    if(c==0){
        float t=red[0]+red[1]+red[2]+red[3]+b2[0];
        out[b]=fmaxf(t,0.f)+log1pf(__expf(-fabsf(t)));
    }
}

extern "C" void kernel_launch(void* const* d_in, const int* in_sizes, int n_in,
                              void* d_out, int out_size){
    (void)in_sizes;(void)n_in;(void)out_size;
    const float* drug_k=(const float*)d_in[0];
    const float* drug_v=(const float*)d_in[1];
    const float* enz_k =(const float*)d_in[2];
    const float* enz_v =(const float*)d_in[3];
    const int*   db    =(const int*)d_in[4];
    const int*   eb    =(const int*)d_in[5];
    const float* lat   =(const float*)d_in[6];
    const float* wq_d=(const float*)d_in[7];  const float* bq_d=(const float*)d_in[8];
    const float* wq_e=(const float*)d_in[9];  const float* bq_e=(const float*)d_in[10];
    const float* mw_d=(const float*)d_in[11]; const float* mb_d=(const float*)d_in[12];
    const float* ow_d=(const float*)d_in[13]; const float* ob_d=(const float*)d_in[14];
    const float* mw_e=(const float*)d_in[15]; const float* mb_e=(const float*)d_in[16];
    const float* ow_e=(const float*)d_in[17]; const float* ob_e=(const float*)d_in[18];
    const float* l1g=(const float*)d_in[19];  const float* l1b=(const float*)d_in[20];
    const float* l2g=(const float*)d_in[21];  const float* l2b=(const float*)d_in[22];
    const float* fw1=(const float*)d_in[23];  const float* fb1=(const float*)d_in[24];
    const float* fw2=(const float*)d_in[25];  const float* fb2=(const float*)d_in[26];
    const float* hw1=(const float*)d_in[27];  const float* hb1=(const float*)d_in[28];
    const float* hw2=(const float*)d_in[29];  const float* hb2=(const float*)d_in[30];
    float* out=(float*)d_out;

    static float *p_lat,*p_nl,*p_qp,*p_u,*p_ffh,*p_h,*p_Qt,*p_qb,*p_M,*p_mb; static int* p_ctr;
    static bool init=false;
    if(!init){
        cudaGetSymbolAddress((void**)&p_lat,g_lat); cudaGetSymbolAddress((void**)&p_nl,g_nl);
        cudaGetSymbolAddress((void**)&p_qp,g_qp);   cudaGetSymbolAddress((void**)&p_u,g_u);
        cudaGetSymbolAddress((void**)&p_ffh,g_ffh); cudaGetSymbolAddress((void**)&p_h,g_h);
        cudaGetSymbolAddress((void**)&p_Qt,g_Qt);   cudaGetSymbolAddress((void**)&p_qb,g_qb);
        cudaGetSymbolAddress((void**)&p_M,g_M);     cudaGetSymbolAddress((void**)&p_mb,g_mb);
        cudaGetSymbolAddress((void**)&p_ctr,g_ctr);
        cudaFuncSetAttribute(k_attn,cudaFuncAttributeMaxDynamicSharedMemorySize,76000);
        init=true;
    }
    k_starts<<<1,1024>>>(db,eb);
    k_pre<<<32,256>>>(mw_d,mb_d,ow_d,ob_d,mw_e,mb_e,ow_e,ob_e);
    k_pre2<<<64,256>>>(wq_d,bq_d,wq_e,bq_e);
    k_init<<<1024,256>>>(lat);

    const int smemA=(RR*DD+2*32*132+32*68)*4;  // 75264
    for(int l=0;l<NLAYER;l++){
        k_ln<<<1024,256>>>(p_lat,p_nl,l1g+l*DD,l1b+l*DD);
        k_gemm<false,false><<<dim3(128,16),256>>>(p_nl,DD,p_Qt+l*1024*DD,DD,p_qp,1024,p_qb+l*1024,DD);
        k_attn<<<444,256,smemA>>>(p_qp,drug_k,drug_v,enz_k,enz_v,p_u,p_ctr+l);
        k_gemm<true,false><<<dim3(128,2),256>>>(p_u,1024,p_M+l*DD*1024,1024,p_lat,DD,p_mb+l*DD,1024);
        k_ln<<<1024,256>>>(p_lat,p_nl,l2g+l*DD,l2b+l*DD);
        k_gemm<false,true><<<dim3(128,4),256>>>(p_nl,DD,fw1+l*2*DD*DD,DD,p_ffh,2*DD,fb1+l*2*DD,DD);
        k_gemm<true,false><<<dim3(128,2),256>>>(p_ffh,2*DD,fw2+l*2*DD*DD,2*DD,p_lat,DD,fb2+l*DD,2*DD);
    }
    k_gemm<false,true><<<dim3(8,2),256>>>(p_lat,NLAT*DD,hw1,NLAT*DD,p_h,DD,hb1,NLAT*DD);
    k_head2<<<BB,128>>>(p_h,hw2,hb2,out);
}

// round 16
// speedup vs baseline: 1.9023x; 1.0542x over previous
#include <cuda_runtime.h>
#include <math.h>

#define BB 512
#define DD 128
#define NLAT 16
#define NLAYER 4
#define NDRUG 25600
#define NENZ 153600
#define RR 64

__device__ float g_lat[BB*NLAT*DD];
__device__ float g_qp [BB*NLAT*1024];   // [8192][1024] both modalities
__device__ float g_u  [BB*NLAT*1024];
__device__ float g_ffh[BB*NLAT*2*DD];
__device__ float g_h  [BB*DD];
__device__ float g_P  [8*DD*512];       // [l][m][cin 128][512]
__device__ float g_pb [8*512];
__device__ float g_Qt [4*1024*DD];      // [l][c 1024][k 128]  (pre-scaled by log2e)
__device__ float g_qb [4*1024];
__device__ float g_M  [4*DD*1024];      // [l][c 128][k 1024]
__device__ float g_mb [4*DD];
__device__ int   g_st [2*(BB+1)];
__device__ int   g_ctr[4];

// ---- packed f32x2 helpers ----
typedef unsigned long long ull;
__device__ __forceinline__ void ffma2(ull &d, ull a, ull b){
    asm("fma.rn.f32x2 %0, %1, %2, %0;" : "+l"(d) : "l"(a), "l"(b));
}
__device__ __forceinline__ void mul2(ull &d, ull s){
    asm("mul.rn.f32x2 %0, %0, %1;" : "+l"(d) : "l"(s));
}
__device__ __forceinline__ ull dup2(float a){
    ull r; asm("mov.b64 %0, {%1,%1};" : "=l"(r) : "f"(a)); return r;
}
__device__ __forceinline__ float2 unp(ull v){
    float2 f; asm("mov.b64 {%0,%1}, %2;" : "=f"(f.x), "=f"(f.y) : "l"(v)); return f;
}
__device__ __forceinline__ float ex2(float x){
    float r; asm("ex2.approx.ftz.f32 %0, %1;" : "=f"(r) : "f"(x)); return r;
}

__device__ __forceinline__ int lowb(const int* a, int n, int v){
    int lo=0, hi=n;
    while(lo<hi){int mid=(lo+hi)>>1; if(a[mid]<v) lo=mid+1; else hi=mid;}
    return lo;
}

__global__ void k_starts(const int* db, const int* eb){
    int b=threadIdx.x;
    if(b<BB){ g_st[b]=lowb(db,NDRUG,b); g_st[BB+1+b]=lowb(eb,NENZ,b); }
    if(b==0){ g_st[BB]=NDRUG; g_st[2*BB+1]=NENZ; }
    if(b<4*DD) g_mb[b]=0.f;
    if(b<4) g_ctr[b]=0;
}

__global__ void k_init(const float* lat){
    int i=blockIdx.x*256+threadIdx.x;
    ((float4*)g_lat)[i]=((const float4*)lat)[i&511];
    if(blockIdx.x<64) ((float4*)g_h)[blockIdx.x*256+threadIdx.x]=make_float4(0.f,0.f,0.f,0.f);
}

// per (l,m,h): P block (Wqm^T Wk /sqrt32), pb, M block (Wo Wv), mb
__global__ void k_pre(const float* mwd,const float* mbd,const float* owd,const float* obd,
                      const float* mwe,const float* mbe,const float* owe,const float* obe){
    int idx=blockIdx.x, l=idx>>3, m=(idx>>2)&1, h=idx&3;
    const float* w =(m?mwe:mwd)+l*3*DD*DD;
    const float* b3=(m?mbe:mbd)+l*3*DD;
    const float* ow=(m?owe:owd)+l*DD*DD;
    const float* ob=(m?obe:obd)+l*DD;
    float* P =g_P +(l*2+m)*DD*512;
    float* pb=g_pb+(l*2+m)*512;
    __shared__ float sA[32*128], sB[32*128];
    int tid=threadIdx.x;
    const float inv=0.17677669529663687f;
    for(int i=tid;i<32*128;i+=256){int j=i>>7,c=i&127;
        sA[i]=w[(h*32+j)*DD+c]; sB[i]=w[(DD+h*32+j)*DD+c];}
    __syncthreads();
    for(int e=tid;e<128*128;e+=256){int c=e>>7,d=e&127; float s=0.f;
        #pragma unroll
        for(int j=0;j<32;j++) s+=sA[j*128+c]*sB[j*128+d];
        P[c*512+h*128+d]=s*inv;}
    if(tid<128){float s=0.f;
        for(int j=0;j<32;j++) s+=b3[h*32+j]*sB[j*128+tid];
        pb[h*128+tid]=s*inv;}
    __syncthreads();
    for(int i=tid;i<32*128;i+=256){int j=i>>7,c=i&127; sB[i]=w[(2*DD+h*32+j)*DD+c];}
    for(int i=tid;i<128*32;i+=256){int c=i>>5,j=i&31; sA[c*32+j]=ow[c*DD+h*32+j];}
    __syncthreads();
    for(int e=tid;e<128*128;e+=256){int c=e>>7,d=e&127; float s=0.f;
        #pragma unroll
        for(int j=0;j<32;j++) s+=sA[c*32+j]*sB[j*128+d];
        g_M[(l*DD+c)*1024 + m*512 + h*128 + d]=s;}
    if(tid<128){float s=(m==0&&h==0)?ob[tid]:0.f;
        for(int j=0;j<32;j++) s+=sA[tid*32+j]*b3[2*DD+h*32+j];
        atomicAdd(&g_mb[l*DD+tid],s);}
}

// Qt[l][c][k] = log2e * sum_j wq[m][j][k]*P[l][m][j][c]; qb = log2e*(bq@P + pb)
__global__ void k_pre2(const float* wqd,const float* bqd,const float* wqe,const float* bqe){
    int idx=blockIdx.x, l=idx>>4, m=(idx>>3)&1, cb=idx&7;
    const float* wq=(m?wqe:wqd)+l*DD*DD;
    const float* bq=(m?bqe:bqd)+l*DD;
    const float* P =g_P +(l*2+m)*DD*512;
    const float L2E=1.4426950408889634f;
    __shared__ float sP[128*64];
    int tid=threadIdx.x;
    for(int i=tid;i<128*64;i+=256){int j=i>>6,cc=i&63; sP[j*64+cc]=P[j*512+cb*64+cc];}
    __syncthreads();
    for(int e=tid;e<64*128;e+=256){
        int cc=e>>7, k=e&127;
        float s=0.f;
        #pragma unroll 8
        for(int j=0;j<128;j++) s+=wq[j*DD+k]*sP[j*64+cc];
        g_Qt[(l*1024 + m*512 + cb*64 + cc)*DD + k]=s*L2E;
    }
    if(tid<64){
        float s=g_pb[(l*2+m)*512 + cb*64 + tid];
        for(int j=0;j<128;j++) s+=bq[j]*sP[j*64+tid];
        g_qb[l*1024 + m*512 + cb*64 + tid]=s*L2E;
    }
}

// K=128 GEMM with fused LayerNorm on A: full-resident A,B tiles, 2 barriers total.
// C[r,c] = act( LN(A[r,:]) @ W[c,:]^T + bias[c] )
template<bool RELU>
__global__ void __launch_bounds__(256) k_gemm128(const float* A,const float* W,
        float* C,int ldc,const float* bias,const float* g,const float* bb){
    extern __shared__ float smem[];
    float* sA=smem;           // 64*132
    float* sB=smem+64*132;    // 64*132
    int rb=blockIdx.x*64, cb=blockIdx.y*64, tid=threadIdx.x;
    int tx=tid&15, ty=tid>>4, wid=tid>>5, lane=tid&31;
    #pragma unroll
    for(int it=0;it<8;it++){
        int i=tid+it*256, row=i>>5, c4=(i&31)<<2;
        *(float4*)&sA[row*132+c4]=*(const float4*)(A+(size_t)(rb+row)*128+c4);
        *(float4*)&sB[row*132+c4]=*(const float4*)(W+(size_t)(cb+row)*128+c4);
    }
    __syncthreads();
    // in-place LN on sA rows (warp per row)
    for(int r=wid;r<64;r+=8){
        float4 v=*(float4*)&sA[r*132+lane*4];
        float s=v.x+v.y+v.z+v.w, s2=v.x*v.x+v.y*v.y+v.z*v.z+v.w*v.w;
        #pragma unroll
        for(int o=16;o;o>>=1){s+=__shfl_xor_sync(~0u,s,o); s2+=__shfl_xor_sync(~0u,s2,o);}
        float m=s*(1.f/128.f), var=s2*(1.f/128.f)-m*m, iv=rsqrtf(var+1e-5f);
        float4 g4=*(const float4*)(g+lane*4), b4=*(const float4*)(bb+lane*4);
        v.x=(v.x-m)*iv*g4.x+b4.x; v.y=(v.y-m)*iv*g4.y+b4.y;
        v.z=(v.z-m)*iv*g4.z+b4.z; v.w=(v.w-m)*iv*g4.w+b4.w;
        *(float4*)&sA[r*132+lane*4]=v;
    }
    __syncthreads();
    ull acc2[4][4]={};
    #pragma unroll 4
    for(int kq=0;kq<128;kq+=4){
        ulonglong2 a[4], b[4];
        #pragma unroll
        for(int j=0;j<4;j++){
            a[j]=*(ulonglong2*)&sA[(ty+16*j)*132+kq];
            b[j]=*(ulonglong2*)&sB[(tx+16*j)*132+kq];
        }
        #pragma unroll
        for(int i=0;i<4;i++)
            #pragma unroll
            for(int j=0;j<4;j++){
                ffma2(acc2[i][j],a[i].x,b[j].x);
                ffma2(acc2[i][j],a[i].y,b[j].y);
            }
    }
    #pragma unroll
    for(int i=0;i<4;i++){
        int r=rb+ty+16*i;
        #pragma unroll
        for(int j=0;j<4;j++){
            int c=cb+tx+16*j;
            float2 f=unp(acc2[i][j]);
            float v=f.x+f.y+bias[c];
            if(RELU) v=fmaxf(v,0.f);
            C[(size_t)r*ldc+c]=v;
        }
    }
}

// chunked GEMM (K arbitrary mult of 32); grid.z = split-K chunks of size K.
template<bool ACC,bool RELU,bool ATOMIC>
__global__ void __launch_bounds__(256) k_gemm(const float* A,int lda,const float* W,int ldw,
                                              float* C,int ldc,const float* bias,int K){
    __shared__ float sA[64*36], sB[64*36];
    int rb=blockIdx.x*64, cb=blockIdx.y*64, tid=threadIdx.x;
    int koff=blockIdx.z*K;
    A+=koff; W+=koff;
    int tx=tid&15, ty=tid>>4;
    ull acc2[4][4]={};
    for(int k0=0;k0<K;k0+=32){
        #pragma unroll
        for(int it=0;it<2;it++){
            int i=tid+it*256, row=i>>3, k4=(i&7)<<2;
            *(float4*)&sA[row*36+k4]=*(const float4*)(A+(size_t)(rb+row)*lda+k0+k4);
            *(float4*)&sB[row*36+k4]=*(const float4*)(W+(size_t)(cb+row)*ldw+k0+k4);
        }
        __syncthreads();
        #pragma unroll
        for(int kq=0;kq<32;kq+=4){
            ulonglong2 a[4], b[4];
            #pragma unroll
            for(int j=0;j<4;j++){
                a[j]=*(ulonglong2*)&sA[(ty+16*j)*36+kq];
                b[j]=*(ulonglong2*)&sB[(tx+16*j)*36+kq];
            }
            #pragma unroll
            for(int i=0;i<4;i++)
                #pragma unroll
                for(int j=0;j<4;j++){
                    ffma2(acc2[i][j],a[i].x,b[j].x);
                    ffma2(acc2[i][j],a[i].y,b[j].y);
                }
        }
        __syncthreads();
    }
    #pragma unroll
    for(int i=0;i<4;i++){
        int r=rb+ty+16*i;
        #pragma unroll
        for(int j=0;j<4;j++){
            int c=cb+tx+16*j;
            float2 f=unp(acc2[i][j]);
            if(ATOMIC){
                atomicAdd(&C[(size_t)r*ldc+c], f.x+f.y);
            }else{
                float v=f.x+f.y+bias[c];
                if(ACC) v+=C[(size_t)r*ldc+c];
                if(RELU) v=fmaxf(v,0.f);
                C[(size_t)r*ldc+c]=v;
            }
        }
    }
}

// persistent flash attention: register-resident softmax state (base-2 domain),
// double-buffered K+V, 2 barriers/tile.
__global__ void __launch_bounds__(256) k_attn(const float* qp,
                                              const float* kd,const float* vd,
                                              const float* ke,const float* ve,
                                              float* u,int* ctr){
    extern __shared__ float sm[];
    float* sQ=sm;               // [64][128]
    float* sK=sm+RR*DD;         // [32][132]
    float* sV=sK+32*132;        // [32][132]
    float* sS=sV+32*132;        // [32 tok][68] transposed exp-scores (warp-local)
    __shared__ int sItem;
    int tid=threadIdx.x;
    int ty=tid>>4, tx=tid&15;
    int c0=tx*4, c1=64+tx*4;    // conflict-free V column groups

    float4 rK[4], rV[4];
    #pragma unroll
    for(int it=0;it<4;it++){ rK[it]=make_float4(0.f,0.f,0.f,0.f); rV[it]=rK[it]; }

    for(;;){
        if(tid==0) sItem=atomicAdd(ctr,1);
        __syncthreads();
        int item=sItem;
        if(item>=1024) break;
        int isE=item<512;              // enzyme first (longer)
        int b=item&511;
        int mcol=isE?512:0;
        const float* kb=isE?ke:kd;
        const float* vb=isE?ve:vd;
        const int* st=g_st+(isE?(BB+1):0);
        int maxLen=isE?512:128;
        int s0=st[b], len=st[b+1]-s0;
        if(len>maxLen) len=maxLen;
        const float* qpb=qp+(size_t)b*NLAT*1024+mcol;
        float* ub=u+(size_t)b*NLAT*1024+mcol;

        if(len==0){
            for(int i=tid;i<RR*DD/4;i+=256){
                int r=i>>5, c4=(i&31)<<2;
                *(float4*)&ub[(size_t)(r>>2)*1024+(r&3)*128+c4]=make_float4(0.f,0.f,0.f,0.f);
            }
            __syncthreads();
            continue;
        }
        for(int i=tid;i<RR*DD/4;i+=256){
            int r=i>>5, c4=(i&31)<<2;
            *(float4*)&sQ[r*DD+c4]=*(const float4*)(qpb+(size_t)(r>>2)*1024+(r&3)*128+c4);
        }
        #pragma unroll
        for(int it=0;it<4;it++){
            int i=tid+it*256, row=i>>5, c4=(i&31)<<2;
            if(row<len){
                rK[it]=*(const float4*)(kb+(size_t)(s0+row)*DD+c4);
                rV[it]=*(const float4*)(vb+(size_t)(s0+row)*DD+c4);
            }
        }

        ull acc[4][4]={};
        float mrow[4], srow[4];
        #pragma unroll
        for(int i=0;i<4;i++){ mrow[i]=-1e30f; srow[i]=0.f; }

        for(int t0=0;t0<len;t0+=32){
            int tc=min(32,len-t0);
            __syncthreads();
            #pragma unroll
            for(int it=0;it<4;it++){
                int i=tid+it*256, row=i>>5, c4=(i&31)<<2;
                *(float4*)&sK[row*132+c4]=rK[it];
                *(float4*)&sV[row*132+c4]=rV[it];
            }
            __syncthreads();
            if(t0+32<len){
                #pragma unroll
                for(int it=0;it<4;it++){
                    int i=tid+it*256, row=i>>5, c4=(i&31)<<2;
                    if(t0+32+row<len){
                        rK[it]=*(const float4*)(kb+(size_t)(s0+t0+32+row)*DD+c4);
                        rV[it]=*(const float4*)(vb+(size_t)(s0+t0+32+row)*DD+c4);
                    }
                }
            }
            ull sc2[4][2]={};
            #pragma unroll 8
            for(int d=0;d<DD;d+=4){
                ulonglong2 k0=*(ulonglong2*)&sK[tx*132+d];
                ulonglong2 k1=*(ulonglong2*)&sK[(tx+16)*132+d];
                #pragma unroll
                for(int i=0;i<4;i++){
                    ulonglong2 q2=*(ulonglong2*)&sQ[(ty*4+i)*DD+d];
                    ffma2(sc2[i][0],q2.x,k0.x); ffma2(sc2[i][0],q2.y,k0.y);
                    ffma2(sc2[i][1],q2.x,k1.x); ffma2(sc2[i][1],q2.y,k1.y);
                }
            }
            // fused online softmax in registers (base-2 domain)
            float scl[4];
            #pragma unroll
            for(int i=0;i<4;i++){
                int r=ty*4+i;
                float2 fa=unp(sc2[i][0]), fb=unp(sc2[i][1]);
                float sA0=(tx<tc)?(fa.x+fa.y):-1e30f;
                float sB0=(tx+16<tc)?(fb.x+fb.y):-1e30f;
                float tm=fmaxf(sA0,sB0);
                #pragma unroll
                for(int o=8;o;o>>=1) tm=fmaxf(tm,__shfl_xor_sync(~0u,tm,o));
                float mNew=fmaxf(mrow[i],tm);
                float e0=ex2(sA0-mNew), e1=ex2(sB0-mNew);
                float ts=e0+e1;
                #pragma unroll
                for(int o=8;o;o>>=1) ts+=__shfl_xor_sync(~0u,ts,o);
                scl[i]=ex2(mrow[i]-mNew);
                srow[i]=srow[i]*scl[i]+ts;
                mrow[i]=mNew;
                sS[tx*68+r]=e0;
                sS[(tx+16)*68+r]=e1;
            }
            __syncwarp();
            #pragma unroll
            for(int i=0;i<4;i++){
                ull s2=dup2(scl[i]);
                #pragma unroll
                for(int p=0;p<4;p++) mul2(acc[i][p],s2);
            }
            for(int t=0;t<tc;t++){
                ulonglong2 v0=*(ulonglong2*)&sV[t*132+c0];
                ulonglong2 v1=*(ulonglong2*)&sV[t*132+c1];
                float4 s4=*(float4*)&sS[t*68+ty*4];
                ull a0=dup2(s4.x), a1=dup2(s4.y), a2=dup2(s4.z), a3=dup2(s4.w);
                ffma2(acc[0][0],a0,v0.x); ffma2(acc[0][1],a0,v0.y);
                ffma2(acc[0][2],a0,v1.x); ffma2(acc[0][3],a0,v1.y);
                ffma2(acc[1][0],a1,v0.x); ffma2(acc[1][1],a1,v0.y);
                ffma2(acc[1][2],a1,v1.x); ffma2(acc[1][3],a1,v1.y);
                ffma2(acc[2][0],a2,v0.x); ffma2(acc[2][1],a2,v0.y);
                ffma2(acc[2][2],a2,v1.x); ffma2(acc[2][3],a2,v1.y);
                ffma2(acc[3][0],a3,v0.x); ffma2(acc[3][1],a3,v0.y);
                ffma2(acc[3][2],a3,v1.x); ffma2(acc[3][3],a3,v1.y);
            }
        }
        #pragma unroll
        for(int i=0;i<4;i++){
            int r=ty*4+i;
            float iv=1.f/srow[i];
            float* base=&ub[(size_t)(r>>2)*1024+(r&3)*128];
            float2 f0=unp(acc[i][0]), f1=unp(acc[i][1]), f2=unp(acc[i][2]), f3=unp(acc[i][3]);
            *(float4*)(base+c0)=make_float4(f0.x*iv,f0.y*iv,f1.x*iv,f1.y*iv);
            *(float4*)(base+c1)=make_float4(f2.x*iv,f2.y*iv,f3.x*iv,f3.y*iv);
        }
        __syncthreads();
    }
}

__global__ void __launch_bounds__(128) k_head2(const float* h,const float* b1,
                                               const float* w2,const float* b2,float* out){
    int b=blockIdx.x, c=threadIdx.x;
    float s=fmaxf(h[(size_t)b*DD+c]+b1[c],0.f)*w2[c];
    #pragma unroll
    for(int o=16;o;o>>=1) s+=__shfl_xor_sync(~0u,s,o);
    __shared__ float red[4];
    if((c&31)==0) red[c>>5]=s;
    __syncthreads();
    if(c==0){
        float t=red[0]+red[1]+red[2]+red[3]+b2[0];
        out[b]=fmaxf(t,0.f)+log1pf(__expf(-fabsf(t)));
    }
}

extern "C" void kernel_launch(void* const* d_in, const int* in_sizes, int n_in,
                              void* d_out, int out_size){
    (void)in_sizes;(void)n_in;(void)out_size;
    const float* drug_k=(const float*)d_in[0];
    const float* drug_v=(const float*)d_in[1];
    const float* enz_k =(const float*)d_in[2];
    const float* enz_v =(const float*)d_in[3];
    const int*   db    =(const int*)d_in[4];
    const int*   eb    =(const int*)d_in[5];
    const float* lat   =(const float*)d_in[6];
    const float* wq_d=(const float*)d_in[7];  const float* bq_d=(const float*)d_in[8];
    const float* wq_e=(const float*)d_in[9];  const float* bq_e=(const float*)d_in[10];
    const float* mw_d=(const float*)d_in[11]; const float* mb_d=(const float*)d_in[12];
    const float* ow_d=(const float*)d_in[13]; const float* ob_d=(const float*)d_in[14];
    const float* mw_e=(const float*)d_in[15]; const float* mb_e=(const float*)d_in[16];
    const float* ow_e=(const float*)d_in[17]; const float* ob_e=(const float*)d_in[18];
    const float* l1g=(const float*)d_in[19];  const float* l1b=(const float*)d_in[20];
    const float* l2g=(const float*)d_in[21];  const float* l2b=(const float*)d_in[22];
    const float* fw1=(const float*)d_in[23];  const float* fb1=(const float*)d_in[24];
    const float* fw2=(const float*)d_in[25];  const float* fb2=(const float*)d_in[26];
    const float* hw1=(const float*)d_in[27];  const float* hb1=(const float*)d_in[28];
    const float* hw2=(const float*)d_in[29];  const float* hb2=(const float*)d_in[30];
    float* out=(float*)d_out;

    static float *p_lat,*p_qp,*p_u,*p_ffh,*p_h,*p_Qt,*p_qb,*p_M,*p_mb; static int* p_ctr;
    static bool init=false;
    if(!init){
        cudaGetSymbolAddress((void**)&p_lat,g_lat);
        cudaGetSymbolAddress((void**)&p_qp,g_qp);   cudaGetSymbolAddress((void**)&p_u,g_u);
        cudaGetSymbolAddress((void**)&p_ffh,g_ffh); cudaGetSymbolAddress((void**)&p_h,g_h);
        cudaGetSymbolAddress((void**)&p_Qt,g_Qt);   cudaGetSymbolAddress((void**)&p_qb,g_qb);
        cudaGetSymbolAddress((void**)&p_M,g_M);     cudaGetSymbolAddress((void**)&p_mb,g_mb);
        cudaGetSymbolAddress((void**)&p_ctr,g_ctr);
        cudaFuncSetAttribute(k_attn,cudaFuncAttributeMaxDynamicSharedMemorySize,76000);
        cudaFuncSetAttribute(k_gemm128<false>,cudaFuncAttributeMaxDynamicSharedMemorySize,68000);
        cudaFuncSetAttribute(k_gemm128<true>, cudaFuncAttributeMaxDynamicSharedMemorySize,68000);
        init=true;
    }
    k_starts<<<1,1024>>>(db,eb);
    k_pre<<<32,256>>>(mw_d,mb_d,ow_d,ob_d,mw_e,mb_e,ow_e,ob_e);
    k_pre2<<<64,256>>>(wq_d,bq_d,wq_e,bq_e);
    k_init<<<1024,256>>>(lat);

    const int smemA=(RR*DD+2*32*132+32*68)*4;  // 75264
    const int smemG=2*64*132*4;                // 67584
    for(int l=0;l<NLAYER;l++){
        // qp = LN1(lat) @ Qt^T + qb   (LN fused)
        k_gemm128<false><<<dim3(128,16),256,smemG>>>(p_lat,p_Qt+l*1024*DD,p_qp,1024,p_qb+l*1024,l1g+l*DD,l1b+l*DD);
        k_attn<<<444,256,smemA>>>(p_qp,drug_k,drug_v,enz_k,enz_v,p_u,p_ctr+l);
        // lat += u @ M^T + mb
        k_gemm<true,false,false><<<dim3(128,2),256>>>(p_u,1024,p_M+l*DD*1024,1024,p_lat,DD,p_mb+l*DD,1024);
        // ffh = relu(LN2(lat) @ fw1^T + fb1)   (LN fused)
        k_gemm128<true><<<dim3(128,4),256,smemG>>>(p_lat,fw1+l*2*DD*DD,p_ffh,2*DD,fb1+l*2*DD,l2g+l*DD,l2b+l*DD);
        // lat += ffh @ fw2^T + fb2
        k_gemm<true,false,false><<<dim3(128,2),256>>>(p_ffh,2*DD,fw2+l*2*DD*DD,2*DD,p_lat,DD,fb2+l*DD,2*DD);
    }
    // head stage 1: split-K atomic accumulate into g_h (zeroed in k_init)
    k_gemm<false,false,true><<<dim3(8,2,8),256>>>(p_lat,NLAT*DD,hw1,NLAT*DD,p_h,DD,hb1,256);
    k_head2<<<BB,128>>>(p_h,hb1,hw2,hb2,out);
}